// round 9
// baseline (speedup 1.0000x reference)
#include <cuda_runtime.h>
#include <cuda_bf16.h>
#include <cuda_fp16.h>
#include <cstdint>

#define NMAX 20000
#define EMAX 320000
#define F 64
#define H 4

typedef unsigned long long u64;

// ------------------- scratch (static device globals; no allocation) -------------------
// fp16 projections, interleaved layout: halves at  n*256 + p*8 + h*2 + k
// (p = g-pair index 0..31, k = element within pair, h = head)
// -> one 16-byte chunk per (n,p) holds all 4 heads of that g-pair.
__device__ __half  g_Rh[NMAX * H * F];
__device__ __half  g_Th[NMAX * H * F];
__device__ float   g_srad[NMAX * H];      // [n][h]
__device__ float   g_stan[NMAX * H];
__device__ float   g_agg[NMAX * F];       // head-averaged aggregate
__device__ float   g_vrad[H * F];         // w_proj @ radial_score
__device__ float   g_vtan[H * F];

// CSR sort scratch
__device__ int     g_cnt[NMAX];
__device__ int     g_off[NMAX + 1];
__device__ int     g_cur[NMAX];
__device__ int     g_ss[EMAX];            // sorted sender
__device__ float   g_sl[EMAX];            // sorted edge_len
__device__ float4  g_er[EMAX];            // exp(rad logit - max) per head
__device__ float4  g_et[EMAX];
__device__ float4  g_w1[EMAX];            // per-edge blended weights
__device__ float4  g_w2[EMAX];

// ------------------- helpers -------------------
__device__ __forceinline__ float softplus_f(float v) {
    return (v > 20.0f) ? v : log1pf(__expf(v));
}
__device__ __forceinline__ float sigmoid_f(float v) {
    return 1.0f / (1.0f + __expf(-v));
}
__device__ __forceinline__ float wred_max(float v) {
#pragma unroll
    for (int d = 16; d; d >>= 1) v = fmaxf(v, __shfl_xor_sync(0xffffffffu, v, d));
    return v;
}
__device__ __forceinline__ float wred_sum(float v) {
#pragma unroll
    for (int d = 16; d; d >>= 1) v += __shfl_xor_sync(0xffffffffu, v, d);
    return v;
}
// packed f32x2 FMA: acc += a * b (two independent fp32 FMAs per issue)
__device__ __forceinline__ void ffma2(u64& acc, u64 a, u64 b) {
    asm("fma.rn.f32x2 %0, %1, %2, %0;" : "+l"(acc) : "l"(a), "l"(b));
}
__device__ __forceinline__ float2 unpack2(u64 v) {
    float2 r;
    asm("mov.b64 {%0, %1}, %2;" : "=f"(r.x), "=f"(r.y) : "l"(v));
    return r;
}

// ------------------- K0: zero counters -------------------
__global__ void k_zero(int n) {
    int i = blockIdx.x * blockDim.x + threadIdx.x;
    if (i < n) g_cnt[i] = 0;
}

// ------------------- K1: score vectors v = W_proj @ score -------------------
__global__ void k_vec(const float* __restrict__ w_proj,
                      const float* __restrict__ rscore,
                      const float* __restrict__ tscore) {
    int tid = threadIdx.x;          // tid = h*64 + f
    int h = tid >> 6;
    const float* wp = w_proj + tid * F;   // w_proj[h][f][:]
    float a = 0.0f, b = 0.0f;
#pragma unroll
    for (int g = 0; g < F; g++) {
        float w = wp[g];
        a += w * rscore[h * F + g];
        b += w * tscore[h * F + g];
    }
    g_vrad[tid] = a;
    g_vtan[tid] = b;
}

// ------------------- K1b: node scalars (fp32) -------------------
__global__ void k_scal(const float* __restrict__ x, int n_nodes) {
    int t = blockIdx.x * blockDim.x + threadIdx.x;
    int n = t >> 2, h = t & 3;
    if (n >= n_nodes) return;
    const float* xr = x + n * F;
    const float* vr = g_vrad + h * F;
    const float* vt = g_vtan + h * F;
    float a = 0.0f, b = 0.0f;
#pragma unroll
    for (int f = 0; f < F; f++) {
        float xv = xr[f];
        a += xv * vr[f];
        b += xv * vt[f];
    }
    g_srad[n * H + h] = a;
    g_stan[n * H + h] = b;
}

// ------------------- K2: projections, FFMA2 (packed f32x2) -------------------
// 512 threads: tid = mat*256 + ng*64 + h*16 + gq.  mat selects R vs T matrix;
// ng owns 8 nodes of the block's 32; (h, gq) owns g = gq*4..gq*4+3 of head h.
// Weights loaded as u64 (packed f32 pair, no pack instrs); x staged in smem
// PRE-DUPLICATED as (v,v) so LDS.64 yields the broadcast multiplier directly.
#define NPB 32
__global__ void __launch_bounds__(512, 2) k_proj(const float* __restrict__ x,
                                                 const float* __restrict__ w_radial,
                                                 const float* __restrict__ w_tang,
                                                 int n_nodes) {
    __shared__ float2 xs[NPB * F];   // 16 KB, duplicated pairs
    int tid = threadIdx.x;
    int mat = tid >> 8;
    int rem = tid & 255;
    int ng = rem >> 6;
    int h  = (rem >> 4) & 3;
    int gq = rem & 15;
    int base = blockIdx.x * NPB;

    for (int i = tid; i < NPB * F; i += 512) {
        int n = base + (i >> 6);
        float v = (n < n_nodes) ? x[n * F + (i & 63)] : 0.0f;
        xs[i] = make_float2(v, v);
    }
    __syncthreads();

    u64 axy[8], azw[8];
#pragma unroll
    for (int j = 0; j < 8; j++) { axy[j] = 0ull; azw[j] = 0ull; }

    const float* w = mat ? w_tang : w_radial;
    // u64 view: row f has 32 u64; this thread's pair columns at gq*2, gq*2+1
    const u64* wq = (const u64*)(w + h * F * F) + gq * 2;
    const u64* xb = (const u64*)&xs[ng * 8 * F];   // per node: F u64 (dup pairs)

#pragma unroll 2
    for (int f = 0; f < F; f += 2) {
        u64 wa0 = __ldg(&wq[f * 32]);        // w(f,   g0g1)
        u64 wa1 = __ldg(&wq[f * 32 + 1]);    // w(f,   g2g3)
        u64 wb0 = __ldg(&wq[f * 32 + 32]);   // w(f+1, g0g1)
        u64 wb1 = __ldg(&wq[f * 32 + 33]);   // w(f+1, g2g3)
#pragma unroll
        for (int j = 0; j < 8; j++) {
            u64 x0 = xb[j * F + f];
            u64 x1 = xb[j * F + f + 1];
            ffma2(axy[j], x0, wa0);
            ffma2(azw[j], x0, wa1);
            ffma2(axy[j], x1, wb0);
            ffma2(azw[j], x1, wb1);
        }
    }

    __half* dstBase = mat ? g_Th : g_Rh;
#pragma unroll
    for (int j = 0; j < 8; j++) {
        int n = base + ng * 8 + j;
        if (n >= n_nodes) break;
        float2 vxy = unpack2(axy[j]);
        float2 vzw = unpack2(azw[j]);
        __half2* d = (__half2*)&dstBase[n * 256];
        int p0 = gq * 2;
        d[p0 * 4 + h]       = __floats2half2_rn(vxy.x, vxy.y);
        d[(p0 + 1) * 4 + h] = __floats2half2_rn(vzw.x, vzw.y);
    }
}

// ------------------- K3: histogram by receiver -------------------
__global__ void k_hist(const int* __restrict__ ei, int n_edges, int n_nodes) {
    int e = blockIdx.x * blockDim.x + threadIdx.x;
    if (e >= n_edges) return;
    int r = ei[n_edges + e];
    if ((unsigned)r < (unsigned)n_nodes) atomicAdd(&g_cnt[r], 1);
}

// ------------------- K4: single-block exclusive scan -------------------
__global__ void k_scan(int n) {
    __shared__ int part[1024];
    int t = threadIdx.x;
    int chunk = (n + 1023) >> 10;
    int b = t * chunk;
    int e = min(b + chunk, n);
    int s = 0;
    for (int i = b; i < e; i++) s += g_cnt[i];
    part[t] = s;
    __syncthreads();
    for (int d = 1; d < 1024; d <<= 1) {
        int v = (t >= d) ? part[t - d] : 0;
        __syncthreads();
        part[t] += v;
        __syncthreads();
    }
    int run = (t > 0) ? part[t - 1] : 0;
    for (int i = b; i < e; i++) {
        g_off[i] = run;
        g_cur[i] = run;
        run += g_cnt[i];
    }
    if (e == n) g_off[n] = run;
}

// ------------------- K5: scatter edges into CSR order -------------------
__global__ void k_sort(const int* __restrict__ ei,
                       const float* __restrict__ elen,
                       int n_edges, int n_nodes) {
    int e = blockIdx.x * blockDim.x + threadIdx.x;
    if (e >= n_edges) return;
    int s = ei[e], r = ei[n_edges + e];
    if ((unsigned)s >= (unsigned)n_nodes || (unsigned)r >= (unsigned)n_nodes) return;
    int pos = atomicAdd(&g_cur[r], 1);
    g_ss[pos] = s;
    g_sl[pos] = elen[e];
}

// ------------------- K6: per-receiver softmax + aggregate (warp per node) -------------------
__global__ void __launch_bounds__(256) k_main(const float* __restrict__ rdls,
                                              const float* __restrict__ rtb,
                                              const float* __restrict__ rtw,
                                              const float* __restrict__ mixb,
                                              const float* __restrict__ mixs,
                                              int n_nodes) {
    int r = (blockIdx.x * blockDim.x + threadIdx.x) >> 5;
    int lane = threadIdx.x & 31;
    if (r >= n_nodes) return;
    int beg = g_off[r], end = g_off[r + 1];

    float2* aggp = (float2*)g_agg;
    if (beg == end) {
        aggp[r * 32 + lane] = make_float2(0.0f, 0.0f);
        return;
    }

    float dist_scale = softplus_f(rdls[0]);
    float4 tb = *(const float4*)rtb;
    float4 tw = *(const float4*)rtw;
    float4 mb = *(const float4*)mixb;
    float4 ms = *(const float4*)mixs;
    float4 srr = *(const float4*)&g_srad[r * 4];
    float4 str = *(const float4*)&g_stan[r * 4];

    const float NEG = __int_as_float(0xff800000);
    float mr0 = NEG, mr1 = NEG, mr2 = NEG, mr3 = NEG;
    float mt0 = NEG, mt1 = NEG, mt2 = NEG, mt3 = NEG;

    // ---- pass A: per-head max ----
    for (int i = beg + lane; i < end; i += 32) {
        int s = g_ss[i];
        float len = g_sl[i];
        float4 ss = *(const float4*)&g_srad[s * 4];
        float4 ts = *(const float4*)&g_stan[s * 4];
        float c = dist_scale * len;
        float t0 = softplus_f(tb.x + tw.x * len) + 1e-4f;
        float t1 = softplus_f(tb.y + tw.y * len) + 1e-4f;
        float t2 = softplus_f(tb.z + tw.z * len) + 1e-4f;
        float t3 = softplus_f(tb.w + tw.w * len) + 1e-4f;
        mr0 = fmaxf(mr0, (ss.x - srr.x - c) / t0);
        mr1 = fmaxf(mr1, (ss.y - srr.y - c) / t1);
        mr2 = fmaxf(mr2, (ss.z - srr.z - c) / t2);
        mr3 = fmaxf(mr3, (ss.w - srr.w - c) / t3);
        mt0 = fmaxf(mt0, ts.x - str.x);
        mt1 = fmaxf(mt1, ts.y - str.y);
        mt2 = fmaxf(mt2, ts.z - str.z);
        mt3 = fmaxf(mt3, ts.w - str.w);
    }
    mr0 = wred_max(mr0); mr1 = wred_max(mr1); mr2 = wred_max(mr2); mr3 = wred_max(mr3);
    mt0 = wred_max(mt0); mt1 = wred_max(mt1); mt2 = wred_max(mt2); mt3 = wred_max(mt3);

    // ---- pass B: exps + denominators ----
    float dr0 = 0, dr1 = 0, dr2 = 0, dr3 = 0;
    float dt0 = 0, dt1 = 0, dt2 = 0, dt3 = 0;
    for (int i = beg + lane; i < end; i += 32) {
        int s = g_ss[i];
        float len = g_sl[i];
        float4 ss = *(const float4*)&g_srad[s * 4];
        float4 ts = *(const float4*)&g_stan[s * 4];
        float c = dist_scale * len;
        float t0 = softplus_f(tb.x + tw.x * len) + 1e-4f;
        float t1 = softplus_f(tb.y + tw.y * len) + 1e-4f;
        float t2 = softplus_f(tb.z + tw.z * len) + 1e-4f;
        float t3 = softplus_f(tb.w + tw.w * len) + 1e-4f;
        float4 er, et;
        er.x = __expf((ss.x - srr.x - c) / t0 - mr0);
        er.y = __expf((ss.y - srr.y - c) / t1 - mr1);
        er.z = __expf((ss.z - srr.z - c) / t2 - mr2);
        er.w = __expf((ss.w - srr.w - c) / t3 - mr3);
        et.x = __expf(ts.x - str.x - mt0);
        et.y = __expf(ts.y - str.y - mt1);
        et.z = __expf(ts.z - str.z - mt2);
        et.w = __expf(ts.w - str.w - mt3);
        g_er[i] = er;
        g_et[i] = et;
        dr0 += er.x; dr1 += er.y; dr2 += er.z; dr3 += er.w;
        dt0 += et.x; dt1 += et.y; dt2 += et.z; dt3 += et.w;
    }
    dr0 = wred_sum(dr0); dr1 = wred_sum(dr1); dr2 = wred_sum(dr2); dr3 = wred_sum(dr3);
    dt0 = wred_sum(dt0); dt1 = wred_sum(dt1); dt2 = wred_sum(dt2); dt3 = wred_sum(dt3);
    dr0 = 1.0f / (dr0 + 1e-9f); dr1 = 1.0f / (dr1 + 1e-9f);
    dr2 = 1.0f / (dr2 + 1e-9f); dr3 = 1.0f / (dr3 + 1e-9f);
    dt0 = 1.0f / (dt0 + 1e-9f); dt1 = 1.0f / (dt1 + 1e-9f);
    dt2 = 1.0f / (dt2 + 1e-9f); dt3 = 1.0f / (dt3 + 1e-9f);

    // ---- pass B2: per-edge blended weights + receiver-side totals (lane-parallel) ----
    float W10 = 0, W11 = 0, W12 = 0, W13 = 0;
    float W20 = 0, W21 = 0, W22 = 0, W23 = 0;
    for (int i = beg + lane; i < end; i += 32) {
        float len = g_sl[i];
        float4 er = g_er[i];
        float4 et = g_et[i];
        float g0 = sigmoid_f(mb.x + ms.x * len);
        float g1 = sigmoid_f(mb.y + ms.y * len);
        float g2 = sigmoid_f(mb.z + ms.z * len);
        float g3 = sigmoid_f(mb.w + ms.w * len);
        float b0 = g0 * er.x * dr0 + (1.0f - g0) * et.x * dt0;
        float b1 = g1 * er.y * dr1 + (1.0f - g1) * et.y * dt1;
        float b2 = g2 * er.z * dr2 + (1.0f - g2) * et.z * dt2;
        float b3 = g3 * er.w * dr3 + (1.0f - g3) * et.w * dt3;
        float4 w1, w2;
        w1.x = b0 * g0; w2.x = b0 * (1.0f - g0);
        w1.y = b1 * g1; w2.y = b1 * (1.0f - g1);
        w1.z = b2 * g2; w2.z = b2 * (1.0f - g2);
        w1.w = b3 * g3; w2.w = b3 * (1.0f - g3);
        g_w1[i] = w1;
        g_w2[i] = w2;
        W10 += w1.x; W11 += w1.y; W12 += w1.z; W13 += w1.w;
        W20 += w2.x; W21 += w2.y; W22 += w2.z; W23 += w2.w;
    }
    W10 = wred_sum(W10); W11 = wred_sum(W11); W12 = wred_sum(W12); W13 = wred_sum(W13);
    W20 = wred_sum(W20); W21 = wred_sum(W21); W22 = wred_sum(W22); W23 = wred_sum(W23);

    // ---- pass C: gather senders, software-pipelined ----
    const uint4* Rp = (const uint4*)g_Rh;   // 16B = all 4 heads of one g-pair
    const uint4* Tp = (const uint4*)g_Th;
    float ax = 0.0f, ay = 0.0f;
    int    s_cur = g_ss[beg];
    float4 w1c   = g_w1[beg];
    float4 w2c   = g_w2[beg];
    for (int i = beg; i < end; i++) {
        uint4 rv = Rp[s_cur * 32 + lane];
        uint4 tv = Tp[s_cur * 32 + lane];
        if (i + 1 < end) {                 // prefetch next edge metadata
            s_cur = g_ss[i + 1];
        }
        float4 w1 = w1c, w2 = w2c;
        if (i + 1 < end) {
            w1c = g_w1[i + 1];
            w2c = g_w2[i + 1];
        }
        const __half2* rh = (const __half2*)&rv;
        const __half2* th = (const __half2*)&tv;
        float2 r0 = __half22float2(rh[0]), r1 = __half22float2(rh[1]);
        float2 r2 = __half22float2(rh[2]), r3 = __half22float2(rh[3]);
        float2 t0 = __half22float2(th[0]), t1 = __half22float2(th[1]);
        float2 t2 = __half22float2(th[2]), t3 = __half22float2(th[3]);
        ax += w1.x * r0.x + w2.x * t0.x + w1.y * r1.x + w2.y * t1.x
            + w1.z * r2.x + w2.z * t2.x + w1.w * r3.x + w2.w * t3.x;
        ay += w1.x * r0.y + w2.x * t0.y + w1.y * r1.y + w2.y * t1.y
            + w1.z * r2.y + w2.z * t2.y + w1.w * r3.y + w2.w * t3.y;
    }
    // subtract factored receiver part
    {
        uint4 rv = Rp[r * 32 + lane];
        uint4 tv = Tp[r * 32 + lane];
        const __half2* rh = (const __half2*)&rv;
        const __half2* th = (const __half2*)&tv;
        float2 r0 = __half22float2(rh[0]), r1 = __half22float2(rh[1]);
        float2 r2 = __half22float2(rh[2]), r3 = __half22float2(rh[3]);
        float2 t0 = __half22float2(th[0]), t1 = __half22float2(th[1]);
        float2 t2 = __half22float2(th[2]), t3 = __half22float2(th[3]);
        ax -= W10 * r0.x + W20 * t0.x + W11 * r1.x + W21 * t1.x
            + W12 * r2.x + W22 * t2.x + W13 * r3.x + W23 * t3.x;
        ay -= W10 * r0.y + W20 * t0.y + W11 * r1.y + W21 * t1.y
            + W12 * r2.y + W22 * t2.y + W13 * r3.y + W23 * t3.y;
    }
    aggp[r * 32 + lane] = make_float2(ax * 0.25f, ay * 0.25f);
}

// ------------------- K7: out = x + agg @ w_out -------------------
#define ONB 4
__global__ void k_out(const float* __restrict__ x,
                      const float* __restrict__ w_out,
                      float* __restrict__ out,
                      int n_nodes) {
    __shared__ float sw[F * F];
    __shared__ float ag[ONB * F];
    int tid = threadIdx.x;
    for (int i = tid; i < F * F; i += 256) sw[i] = w_out[i];
    int nl = tid >> 6, g = tid & 63;
    int n = blockIdx.x * ONB + nl;
    if (n < n_nodes) ag[nl * F + g] = g_agg[n * F + g];
    __syncthreads();
    if (n >= n_nodes) return;
    float acc = x[n * F + g];
#pragma unroll
    for (int f = 0; f < F; f++) acc += ag[nl * F + f] * sw[f * F + g];
    out[n * F + g] = acc;
}

// ------------------- launch -------------------
extern "C" void kernel_launch(void* const* d_in, const int* in_sizes, int n_in,
                              void* d_out, int out_size) {
    const float* x     = (const float*)d_in[0];
    const int*   ei    = (const int*)d_in[1];     // edge_index staged as int32, [2, E]
    // d_in[2] = edge_vec (unused by reference)
    const float* elen  = (const float*)d_in[3];
    const float* wprj  = (const float*)d_in[4];
    const float* wrad  = (const float*)d_in[5];
    const float* wtan  = (const float*)d_in[6];
    const float* rsc   = (const float*)d_in[7];
    const float* tsc   = (const float*)d_in[8];
    const float* rdls  = (const float*)d_in[9];
    const float* rtb   = (const float*)d_in[10];
    const float* rtw   = (const float*)d_in[11];
    const float* mixb  = (const float*)d_in[12];
    const float* mixs  = (const float*)d_in[13];
    const float* wout  = (const float*)d_in[14];
    float*       out   = (float*)d_out;

    int n_nodes = in_sizes[0] / F;
    int n_edges = in_sizes[3];

    k_zero<<<(n_nodes + 255) / 256, 256>>>(n_nodes);
    k_vec<<<1, H * F>>>(wprj, rsc, tsc);
    k_scal<<<(n_nodes * H + 255) / 256, 256>>>(x, n_nodes);

    k_proj<<<(n_nodes + NPB - 1) / NPB, 512>>>(x, wrad, wtan, n_nodes);

    k_hist<<<(n_edges + 255) / 256, 256>>>(ei, n_edges, n_nodes);
    k_scan<<<1, 1024>>>(n_nodes);
    k_sort<<<(n_edges + 255) / 256, 256>>>(ei, elen, n_edges, n_nodes);

    k_main<<<(n_nodes * 32 + 255) / 256, 256>>>(rdls, rtb, rtw, mixb, mixs, n_nodes);
    k_out<<<(n_nodes + ONB - 1) / ONB, 256>>>(x, wout, out, n_nodes);
}

// round 10
// speedup vs baseline: 1.0103x; 1.0103x over previous
#include <cuda_runtime.h>
#include <cuda_bf16.h>
#include <cuda_fp16.h>
#include <cstdint>

#define NMAX 20000
#define EMAX 320000
#define F 64
#define H 4

typedef unsigned long long u64;

// ------------------- scratch (static device globals; no allocation) -------------------
// fp16 projections, interleaved layout: halves at  n*256 + p*8 + h*2 + k
// (p = g-pair index 0..31, k = element within pair, h = head)
// -> one 16-byte chunk per (n,p) holds all 4 heads of that g-pair.
__device__ __half  g_Rh[NMAX * H * F];
__device__ __half  g_Th[NMAX * H * F];
__device__ float   g_srad[NMAX * H];      // [n][h]
__device__ float   g_stan[NMAX * H];
__device__ float   g_agg[NMAX * F];       // head-averaged aggregate
__device__ float   g_vrad[H * F];         // w_proj @ radial_score
__device__ float   g_vtan[H * F];

// CSR sort scratch
__device__ int     g_cnt[NMAX];
__device__ int     g_off[NMAX + 1];
__device__ int     g_cur[NMAX];
__device__ int     g_ss[EMAX];            // sorted sender
__device__ float   g_sl[EMAX];            // sorted edge_len
__device__ float4  g_er[EMAX];            // exp(rad logit - max) per head
__device__ float4  g_et[EMAX];
__device__ float4  g_w1[EMAX];            // per-edge blended weights
__device__ float4  g_w2[EMAX];

// ------------------- helpers -------------------
__device__ __forceinline__ float softplus_f(float v) {
    return (v > 20.0f) ? v : log1pf(__expf(v));
}
__device__ __forceinline__ float sigmoid_f(float v) {
    return 1.0f / (1.0f + __expf(-v));
}
__device__ __forceinline__ float wred_max(float v) {
#pragma unroll
    for (int d = 16; d; d >>= 1) v = fmaxf(v, __shfl_xor_sync(0xffffffffu, v, d));
    return v;
}
__device__ __forceinline__ float wred_sum(float v) {
#pragma unroll
    for (int d = 16; d; d >>= 1) v += __shfl_xor_sync(0xffffffffu, v, d);
    return v;
}
// packed f32x2 FMA: acc += a * b (two independent fp32 FMAs per issue)
__device__ __forceinline__ void ffma2(u64& acc, u64 a, u64 b) {
    asm("fma.rn.f32x2 %0, %1, %2, %0;" : "+l"(acc) : "l"(a), "l"(b));
}
__device__ __forceinline__ float2 unpack2(u64 v) {
    float2 r;
    asm("mov.b64 {%0, %1}, %2;" : "=f"(r.x), "=f"(r.y) : "l"(v));
    return r;
}

// ------------------- K0: zero counters -------------------
__global__ void k_zero(int n) {
    int i = blockIdx.x * blockDim.x + threadIdx.x;
    if (i < n) g_cnt[i] = 0;
}

// ------------------- K1: score vectors v = W_proj @ score -------------------
__global__ void k_vec(const float* __restrict__ w_proj,
                      const float* __restrict__ rscore,
                      const float* __restrict__ tscore) {
    int tid = threadIdx.x;          // tid = h*64 + f
    int h = tid >> 6;
    const float* wp = w_proj + tid * F;   // w_proj[h][f][:]
    float a = 0.0f, b = 0.0f;
#pragma unroll
    for (int g = 0; g < F; g++) {
        float w = wp[g];
        a += w * rscore[h * F + g];
        b += w * tscore[h * F + g];
    }
    g_vrad[tid] = a;
    g_vtan[tid] = b;
}

// ------------------- K1b: node scalars (fp32) -------------------
__global__ void k_scal(const float* __restrict__ x, int n_nodes) {
    int t = blockIdx.x * blockDim.x + threadIdx.x;
    int n = t >> 2, h = t & 3;
    if (n >= n_nodes) return;
    const float* xr = x + n * F;
    const float* vr = g_vrad + h * F;
    const float* vt = g_vtan + h * F;
    float a = 0.0f, b = 0.0f;
#pragma unroll
    for (int f = 0; f < F; f++) {
        float xv = xr[f];
        a += xv * vr[f];
        b += xv * vt[f];
    }
    g_srad[n * H + h] = a;
    g_stan[n * H + h] = b;
}

// ------------------- K2: projections, FFMA2 fed by LDS.128 -------------------
// 512 threads: tid = mat*256 + ng*64 + h*16 + gq.  mat selects R vs T matrix;
// ng owns 8 nodes of the block's 32; (h, gq) owns g = gq*4..gq*4+3 of head h.
// x staged in smem as duplicated pairs (v_f,v_f,v_{f+1},v_{f+1}) so one
// broadcast LDS.128 yields BOTH packed f32x2 multiplicands for a 2-f step.
// Weights fetched as LDG.128 (two adjacent u64 packed pairs per row).
#define NPB 32
__global__ void __launch_bounds__(512, 2) k_proj(const float* __restrict__ x,
                                                 const float* __restrict__ w_radial,
                                                 const float* __restrict__ w_tang,
                                                 int n_nodes) {
    __shared__ float2 xs[NPB * F];   // 16 KB, duplicated pairs
    int tid = threadIdx.x;
    int mat = tid >> 8;
    int rem = tid & 255;
    int ng = rem >> 6;
    int h  = (rem >> 4) & 3;
    int gq = rem & 15;
    int base = blockIdx.x * NPB;

    for (int i = tid; i < NPB * F; i += 512) {
        int n = base + (i >> 6);
        float v = (n < n_nodes) ? x[n * F + (i & 63)] : 0.0f;
        xs[i] = make_float2(v, v);
    }
    __syncthreads();

    u64 axy[8], azw[8];
#pragma unroll
    for (int j = 0; j < 8; j++) { axy[j] = 0ull; azw[j] = 0ull; }

    const float* w = mat ? w_tang : w_radial;
    // uint4 view of weights: row f has 16 uint4; this thread's 16B at column gq.
    const uint4* wq = (const uint4*)(w + h * F * F) + gq;
    // uint4 view of x dup-pairs: per node F/2 uint4 (one per 2-f step).
    const uint4* xb = (const uint4*)&xs[ng * 8 * F];

#pragma unroll 4
    for (int f2 = 0; f2 < F / 2; f2++) {
        uint4 wa = __ldg(&wq[(2 * f2) * 16]);        // row f:   (g0g1, g2g3)
        uint4 wb = __ldg(&wq[(2 * f2 + 1) * 16]);    // row f+1: (g0g1, g2g3)
        u64 wa0 = *(const u64*)&wa.x, wa1 = *(const u64*)&wa.z;
        u64 wb0 = *(const u64*)&wb.x, wb1 = *(const u64*)&wb.z;
#pragma unroll
        for (int j = 0; j < 8; j++) {
            uint4 xv = xb[j * (F / 2) + f2];         // (x_f dup, x_{f+1} dup)
            u64 x0 = *(const u64*)&xv.x;
            u64 x1 = *(const u64*)&xv.z;
            ffma2(axy[j], x0, wa0);
            ffma2(azw[j], x0, wa1);
            ffma2(axy[j], x1, wb0);
            ffma2(azw[j], x1, wb1);
        }
    }

    __half* dstBase = mat ? g_Th : g_Rh;
#pragma unroll
    for (int j = 0; j < 8; j++) {
        int n = base + ng * 8 + j;
        if (n >= n_nodes) break;
        float2 vxy = unpack2(axy[j]);
        float2 vzw = unpack2(azw[j]);
        __half2* d = (__half2*)&dstBase[n * 256];
        int p0 = gq * 2;
        d[p0 * 4 + h]       = __floats2half2_rn(vxy.x, vxy.y);
        d[(p0 + 1) * 4 + h] = __floats2half2_rn(vzw.x, vzw.y);
    }
}

// ------------------- K3: histogram by receiver -------------------
__global__ void k_hist(const int* __restrict__ ei, int n_edges, int n_nodes) {
    int e = blockIdx.x * blockDim.x + threadIdx.x;
    if (e >= n_edges) return;
    int r = ei[n_edges + e];
    if ((unsigned)r < (unsigned)n_nodes) atomicAdd(&g_cnt[r], 1);
}

// ------------------- K4: single-block exclusive scan -------------------
__global__ void k_scan(int n) {
    __shared__ int part[1024];
    int t = threadIdx.x;
    int chunk = (n + 1023) >> 10;
    int b = t * chunk;
    int e = min(b + chunk, n);
    int s = 0;
    for (int i = b; i < e; i++) s += g_cnt[i];
    part[t] = s;
    __syncthreads();
    for (int d = 1; d < 1024; d <<= 1) {
        int v = (t >= d) ? part[t - d] : 0;
        __syncthreads();
        part[t] += v;
        __syncthreads();
    }
    int run = (t > 0) ? part[t - 1] : 0;
    for (int i = b; i < e; i++) {
        g_off[i] = run;
        g_cur[i] = run;
        run += g_cnt[i];
    }
    if (e == n) g_off[n] = run;
}

// ------------------- K5: scatter edges into CSR order -------------------
__global__ void k_sort(const int* __restrict__ ei,
                       const float* __restrict__ elen,
                       int n_edges, int n_nodes) {
    int e = blockIdx.x * blockDim.x + threadIdx.x;
    if (e >= n_edges) return;
    int s = ei[e], r = ei[n_edges + e];
    if ((unsigned)s >= (unsigned)n_nodes || (unsigned)r >= (unsigned)n_nodes) return;
    int pos = atomicAdd(&g_cur[r], 1);
    g_ss[pos] = s;
    g_sl[pos] = elen[e];
}

// ------------------- K6: per-receiver softmax + aggregate (warp per node) -------------------
__global__ void __launch_bounds__(256) k_main(const float* __restrict__ rdls,
                                              const float* __restrict__ rtb,
                                              const float* __restrict__ rtw,
                                              const float* __restrict__ mixb,
                                              const float* __restrict__ mixs,
                                              int n_nodes) {
    int r = (blockIdx.x * blockDim.x + threadIdx.x) >> 5;
    int lane = threadIdx.x & 31;
    if (r >= n_nodes) return;
    int beg = g_off[r], end = g_off[r + 1];

    float2* aggp = (float2*)g_agg;
    if (beg == end) {
        aggp[r * 32 + lane] = make_float2(0.0f, 0.0f);
        return;
    }

    float dist_scale = softplus_f(rdls[0]);
    float4 tb = *(const float4*)rtb;
    float4 tw = *(const float4*)rtw;
    float4 mb = *(const float4*)mixb;
    float4 ms = *(const float4*)mixs;
    float4 srr = *(const float4*)&g_srad[r * 4];
    float4 str = *(const float4*)&g_stan[r * 4];

    const float NEG = __int_as_float(0xff800000);
    float mr0 = NEG, mr1 = NEG, mr2 = NEG, mr3 = NEG;
    float mt0 = NEG, mt1 = NEG, mt2 = NEG, mt3 = NEG;

    // ---- pass A: per-head max ----
    for (int i = beg + lane; i < end; i += 32) {
        int s = g_ss[i];
        float len = g_sl[i];
        float4 ss = *(const float4*)&g_srad[s * 4];
        float4 ts = *(const float4*)&g_stan[s * 4];
        float c = dist_scale * len;
        float t0 = softplus_f(tb.x + tw.x * len) + 1e-4f;
        float t1 = softplus_f(tb.y + tw.y * len) + 1e-4f;
        float t2 = softplus_f(tb.z + tw.z * len) + 1e-4f;
        float t3 = softplus_f(tb.w + tw.w * len) + 1e-4f;
        mr0 = fmaxf(mr0, (ss.x - srr.x - c) / t0);
        mr1 = fmaxf(mr1, (ss.y - srr.y - c) / t1);
        mr2 = fmaxf(mr2, (ss.z - srr.z - c) / t2);
        mr3 = fmaxf(mr3, (ss.w - srr.w - c) / t3);
        mt0 = fmaxf(mt0, ts.x - str.x);
        mt1 = fmaxf(mt1, ts.y - str.y);
        mt2 = fmaxf(mt2, ts.z - str.z);
        mt3 = fmaxf(mt3, ts.w - str.w);
    }
    mr0 = wred_max(mr0); mr1 = wred_max(mr1); mr2 = wred_max(mr2); mr3 = wred_max(mr3);
    mt0 = wred_max(mt0); mt1 = wred_max(mt1); mt2 = wred_max(mt2); mt3 = wred_max(mt3);

    // ---- pass B: exps + denominators ----
    float dr0 = 0, dr1 = 0, dr2 = 0, dr3 = 0;
    float dt0 = 0, dt1 = 0, dt2 = 0, dt3 = 0;
    for (int i = beg + lane; i < end; i += 32) {
        int s = g_ss[i];
        float len = g_sl[i];
        float4 ss = *(const float4*)&g_srad[s * 4];
        float4 ts = *(const float4*)&g_stan[s * 4];
        float c = dist_scale * len;
        float t0 = softplus_f(tb.x + tw.x * len) + 1e-4f;
        float t1 = softplus_f(tb.y + tw.y * len) + 1e-4f;
        float t2 = softplus_f(tb.z + tw.z * len) + 1e-4f;
        float t3 = softplus_f(tb.w + tw.w * len) + 1e-4f;
        float4 er, et;
        er.x = __expf((ss.x - srr.x - c) / t0 - mr0);
        er.y = __expf((ss.y - srr.y - c) / t1 - mr1);
        er.z = __expf((ss.z - srr.z - c) / t2 - mr2);
        er.w = __expf((ss.w - srr.w - c) / t3 - mr3);
        et.x = __expf(ts.x - str.x - mt0);
        et.y = __expf(ts.y - str.y - mt1);
        et.z = __expf(ts.z - str.z - mt2);
        et.w = __expf(ts.w - str.w - mt3);
        g_er[i] = er;
        g_et[i] = et;
        dr0 += er.x; dr1 += er.y; dr2 += er.z; dr3 += er.w;
        dt0 += et.x; dt1 += et.y; dt2 += et.z; dt3 += et.w;
    }
    dr0 = wred_sum(dr0); dr1 = wred_sum(dr1); dr2 = wred_sum(dr2); dr3 = wred_sum(dr3);
    dt0 = wred_sum(dt0); dt1 = wred_sum(dt1); dt2 = wred_sum(dt2); dt3 = wred_sum(dt3);
    dr0 = 1.0f / (dr0 + 1e-9f); dr1 = 1.0f / (dr1 + 1e-9f);
    dr2 = 1.0f / (dr2 + 1e-9f); dr3 = 1.0f / (dr3 + 1e-9f);
    dt0 = 1.0f / (dt0 + 1e-9f); dt1 = 1.0f / (dt1 + 1e-9f);
    dt2 = 1.0f / (dt2 + 1e-9f); dt3 = 1.0f / (dt3 + 1e-9f);

    // ---- pass B2: per-edge blended weights + receiver-side totals (lane-parallel) ----
    float W10 = 0, W11 = 0, W12 = 0, W13 = 0;
    float W20 = 0, W21 = 0, W22 = 0, W23 = 0;
    for (int i = beg + lane; i < end; i += 32) {
        float len = g_sl[i];
        float4 er = g_er[i];
        float4 et = g_et[i];
        float g0 = sigmoid_f(mb.x + ms.x * len);
        float g1 = sigmoid_f(mb.y + ms.y * len);
        float g2 = sigmoid_f(mb.z + ms.z * len);
        float g3 = sigmoid_f(mb.w + ms.w * len);
        float b0 = g0 * er.x * dr0 + (1.0f - g0) * et.x * dt0;
        float b1 = g1 * er.y * dr1 + (1.0f - g1) * et.y * dt1;
        float b2 = g2 * er.z * dr2 + (1.0f - g2) * et.z * dt2;
        float b3 = g3 * er.w * dr3 + (1.0f - g3) * et.w * dt3;
        float4 w1, w2;
        w1.x = b0 * g0; w2.x = b0 * (1.0f - g0);
        w1.y = b1 * g1; w2.y = b1 * (1.0f - g1);
        w1.z = b2 * g2; w2.z = b2 * (1.0f - g2);
        w1.w = b3 * g3; w2.w = b3 * (1.0f - g3);
        g_w1[i] = w1;
        g_w2[i] = w2;
        W10 += w1.x; W11 += w1.y; W12 += w1.z; W13 += w1.w;
        W20 += w2.x; W21 += w2.y; W22 += w2.z; W23 += w2.w;
    }
    W10 = wred_sum(W10); W11 = wred_sum(W11); W12 = wred_sum(W12); W13 = wred_sum(W13);
    W20 = wred_sum(W20); W21 = wred_sum(W21); W22 = wred_sum(W22); W23 = wred_sum(W23);

    // ---- pass C: gather senders, software-pipelined ----
    const uint4* Rp = (const uint4*)g_Rh;   // 16B = all 4 heads of one g-pair
    const uint4* Tp = (const uint4*)g_Th;
    float ax = 0.0f, ay = 0.0f;
    int    s_cur = g_ss[beg];
    float4 w1c   = g_w1[beg];
    float4 w2c   = g_w2[beg];
    for (int i = beg; i < end; i++) {
        uint4 rv = Rp[s_cur * 32 + lane];
        uint4 tv = Tp[s_cur * 32 + lane];
        if (i + 1 < end) {                 // prefetch next edge metadata
            s_cur = g_ss[i + 1];
        }
        float4 w1 = w1c, w2 = w2c;
        if (i + 1 < end) {
            w1c = g_w1[i + 1];
            w2c = g_w2[i + 1];
        }
        const __half2* rh = (const __half2*)&rv;
        const __half2* th = (const __half2*)&tv;
        float2 r0 = __half22float2(rh[0]), r1 = __half22float2(rh[1]);
        float2 r2 = __half22float2(rh[2]), r3 = __half22float2(rh[3]);
        float2 t0 = __half22float2(th[0]), t1 = __half22float2(th[1]);
        float2 t2 = __half22float2(th[2]), t3 = __half22float2(th[3]);
        ax += w1.x * r0.x + w2.x * t0.x + w1.y * r1.x + w2.y * t1.x
            + w1.z * r2.x + w2.z * t2.x + w1.w * r3.x + w2.w * t3.x;
        ay += w1.x * r0.y + w2.x * t0.y + w1.y * r1.y + w2.y * t1.y
            + w1.z * r2.y + w2.z * t2.y + w1.w * r3.y + w2.w * t3.y;
    }
    // subtract factored receiver part
    {
        uint4 rv = Rp[r * 32 + lane];
        uint4 tv = Tp[r * 32 + lane];
        const __half2* rh = (const __half2*)&rv;
        const __half2* th = (const __half2*)&tv;
        float2 r0 = __half22float2(rh[0]), r1 = __half22float2(rh[1]);
        float2 r2 = __half22float2(rh[2]), r3 = __half22float2(rh[3]);
        float2 t0 = __half22float2(th[0]), t1 = __half22float2(th[1]);
        float2 t2 = __half22float2(th[2]), t3 = __half22float2(th[3]);
        ax -= W10 * r0.x + W20 * t0.x + W11 * r1.x + W21 * t1.x
            + W12 * r2.x + W22 * t2.x + W13 * r3.x + W23 * t3.x;
        ay -= W10 * r0.y + W20 * t0.y + W11 * r1.y + W21 * t1.y
            + W12 * r2.y + W22 * t2.y + W13 * r3.y + W23 * t3.y;
    }
    aggp[r * 32 + lane] = make_float2(ax * 0.25f, ay * 0.25f);
}

// ------------------- K7: out = x + agg @ w_out -------------------
#define ONB 4
__global__ void k_out(const float* __restrict__ x,
                      const float* __restrict__ w_out,
                      float* __restrict__ out,
                      int n_nodes) {
    __shared__ float sw[F * F];
    __shared__ float ag[ONB * F];
    int tid = threadIdx.x;
    for (int i = tid; i < F * F; i += 256) sw[i] = w_out[i];
    int nl = tid >> 6, g = tid & 63;
    int n = blockIdx.x * ONB + nl;
    if (n < n_nodes) ag[nl * F + g] = g_agg[n * F + g];
    __syncthreads();
    if (n >= n_nodes) return;
    float acc = x[n * F + g];
#pragma unroll
    for (int f = 0; f < F; f++) acc += ag[nl * F + f] * sw[f * F + g];
    out[n * F + g] = acc;
}

// ------------------- launch -------------------
extern "C" void kernel_launch(void* const* d_in, const int* in_sizes, int n_in,
                              void* d_out, int out_size) {
    const float* x     = (const float*)d_in[0];
    const int*   ei    = (const int*)d_in[1];     // edge_index staged as int32, [2, E]
    // d_in[2] = edge_vec (unused by reference)
    const float* elen  = (const float*)d_in[3];
    const float* wprj  = (const float*)d_in[4];
    const float* wrad  = (const float*)d_in[5];
    const float* wtan  = (const float*)d_in[6];
    const float* rsc   = (const float*)d_in[7];
    const float* tsc   = (const float*)d_in[8];
    const float* rdls  = (const float*)d_in[9];
    const float* rtb   = (const float*)d_in[10];
    const float* rtw   = (const float*)d_in[11];
    const float* mixb  = (const float*)d_in[12];
    const float* mixs  = (const float*)d_in[13];
    const float* wout  = (const float*)d_in[14];
    float*       out   = (float*)d_out;

    int n_nodes = in_sizes[0] / F;
    int n_edges = in_sizes[3];

    k_zero<<<(n_nodes + 255) / 256, 256>>>(n_nodes);
    k_vec<<<1, H * F>>>(wprj, rsc, tsc);
    k_scal<<<(n_nodes * H + 255) / 256, 256>>>(x, n_nodes);

    k_proj<<<(n_nodes + NPB - 1) / NPB, 512>>>(x, wrad, wtan, n_nodes);

    k_hist<<<(n_edges + 255) / 256, 256>>>(ei, n_edges, n_nodes);
    k_scan<<<1, 1024>>>(n_nodes);
    k_sort<<<(n_edges + 255) / 256, 256>>>(ei, elen, n_edges, n_nodes);

    k_main<<<(n_nodes * 32 + 255) / 256, 256>>>(rdls, rtb, rtw, mixb, mixs, n_nodes);
    k_out<<<(n_nodes + ONB - 1) / ONB, 256>>>(x, wout, out, n_nodes);
}

// round 11
// speedup vs baseline: 1.0782x; 1.0672x over previous
#include <cuda_runtime.h>
#include <cuda_bf16.h>
#include <cuda_fp16.h>
#include <cstdint>

#define NMAX 20000
#define EMAX 320000
#define F 64
#define H 4

// ------------------- scratch (static device globals; no allocation) -------------------
// fp16 projections, interleaved layout: halves at  n*256 + p*8 + h*2 + k
// (p = g-pair index 0..31, k = element within pair, h = head)
// -> one 16-byte chunk per (n,p) holds all 4 heads of that g-pair.
__device__ __half  g_Rh[NMAX * H * F];
__device__ __half  g_Th[NMAX * H * F];
__device__ float   g_srad[NMAX * H];      // [n][h]
__device__ float   g_stan[NMAX * H];
__device__ float   g_agg[NMAX * F];       // head-averaged aggregate
__device__ float   g_vrad[H * F];         // w_proj @ radial_score
__device__ float   g_vtan[H * F];

// CSR sort scratch
__device__ int     g_cnt[NMAX];
__device__ int     g_off[NMAX + 1];
__device__ int     g_cur[NMAX];
__device__ int     g_ss[EMAX];            // sorted sender
__device__ float   g_sl[EMAX];            // sorted edge_len
__device__ float4  g_er[EMAX];            // pass A: radial logits; pass B: exps
__device__ float4  g_et[EMAX];            // pass A: tangential logits; pass B: exps
__device__ float4  g_w1[EMAX];            // per-edge blended weights
__device__ float4  g_w2[EMAX];

// ------------------- helpers -------------------
__device__ __forceinline__ float softplus_f(float v) {
    return (v > 20.0f) ? v : log1pf(__expf(v));
}
__device__ __forceinline__ float sigmoid_f(float v) {
    return 1.0f / (1.0f + __expf(-v));
}
__device__ __forceinline__ float wred_max(float v) {
#pragma unroll
    for (int d = 16; d; d >>= 1) v = fmaxf(v, __shfl_xor_sync(0xffffffffu, v, d));
    return v;
}
__device__ __forceinline__ float wred_sum(float v) {
#pragma unroll
    for (int d = 16; d; d >>= 1) v += __shfl_xor_sync(0xffffffffu, v, d);
    return v;
}

// ------------------- K0: zero counters -------------------
__global__ void k_zero(int n) {
    int i = blockIdx.x * blockDim.x + threadIdx.x;
    if (i < n) g_cnt[i] = 0;
}

// ------------------- K1: score vectors v = W_proj @ score -------------------
__global__ void k_vec(const float* __restrict__ w_proj,
                      const float* __restrict__ rscore,
                      const float* __restrict__ tscore) {
    int tid = threadIdx.x;          // tid = h*64 + f
    int h = tid >> 6;
    const float* wp = w_proj + tid * F;   // w_proj[h][f][:]
    float a = 0.0f, b = 0.0f;
#pragma unroll
    for (int g = 0; g < F; g++) {
        float w = wp[g];
        a += w * rscore[h * F + g];
        b += w * tscore[h * F + g];
    }
    g_vrad[tid] = a;
    g_vtan[tid] = b;
}

// ------------------- K1b: node scalars (fp32) -------------------
__global__ void k_scal(const float* __restrict__ x, int n_nodes) {
    int t = blockIdx.x * blockDim.x + threadIdx.x;
    int n = t >> 2, h = t & 3;
    if (n >= n_nodes) return;
    const float* xr = x + n * F;
    const float* vr = g_vrad + h * F;
    const float* vt = g_vtan + h * F;
    float a = 0.0f, b = 0.0f;
#pragma unroll
    for (int f = 0; f < F; f++) {
        float xv = xr[f];
        a += xv * vr[f];
        b += xv * vt[f];
    }
    g_srad[n * H + h] = a;
    g_stan[n * H + h] = b;
}

// ------------------- K2: projections, R/T split across threads (R8 form) ----
// 512 threads: tid = mat*256 + ng*64 + h*16 + gq.  mat selects R vs T matrix;
// ng owns 8 nodes of the block's 32; (h, gq) owns g = gq*4..gq*4+3 of head h.
// f-loop in chunks of 4: 4x LDG.128 weights (MLP=4) + broadcast LDS.128 x.
#define NPB 32
__global__ void __launch_bounds__(512, 2) k_proj(const float* __restrict__ x,
                                                 const float* __restrict__ w_radial,
                                                 const float* __restrict__ w_tang,
                                                 int n_nodes) {
    __shared__ float xs[NPB * F];
    int tid = threadIdx.x;
    int mat = tid >> 8;
    int rem = tid & 255;
    int ng = rem >> 6;
    int h  = (rem >> 4) & 3;
    int gq = rem & 15;
    int base = blockIdx.x * NPB;

    for (int i = tid; i < NPB * F; i += 512) {
        int n = base + (i >> 6);
        xs[i] = (n < n_nodes) ? x[n * F + (i & 63)] : 0.0f;
    }
    __syncthreads();

    float4 acc[8];
#pragma unroll
    for (int j = 0; j < 8; j++) acc[j] = make_float4(0.f, 0.f, 0.f, 0.f);

    const float* w = mat ? w_tang : w_radial;
    const float4* w4 = (const float4*)(w + h * F * F) + gq;
    const float*  xb = &xs[ng * 8 * F];

    for (int fc = 0; fc < F; fc += 4) {
        float4 wv0 = __ldg(&w4[(fc + 0) * 16]);
        float4 wv1 = __ldg(&w4[(fc + 1) * 16]);
        float4 wv2 = __ldg(&w4[(fc + 2) * 16]);
        float4 wv3 = __ldg(&w4[(fc + 3) * 16]);
#pragma unroll
        for (int j = 0; j < 8; j++) {
            float4 xv = *(const float4*)&xb[j * F + fc];
            acc[j].x += xv.x * wv0.x + xv.y * wv1.x + xv.z * wv2.x + xv.w * wv3.x;
            acc[j].y += xv.x * wv0.y + xv.y * wv1.y + xv.z * wv2.y + xv.w * wv3.y;
            acc[j].z += xv.x * wv0.z + xv.y * wv1.z + xv.z * wv2.z + xv.w * wv3.z;
            acc[j].w += xv.x * wv0.w + xv.y * wv1.w + xv.z * wv2.w + xv.w * wv3.w;
        }
    }

    __half* dstBase = mat ? g_Th : g_Rh;
#pragma unroll
    for (int j = 0; j < 8; j++) {
        int n = base + ng * 8 + j;
        if (n >= n_nodes) break;
        __half2* d = (__half2*)&dstBase[n * 256];
        int p0 = gq * 2;
        d[p0 * 4 + h]       = __floats2half2_rn(acc[j].x, acc[j].y);
        d[(p0 + 1) * 4 + h] = __floats2half2_rn(acc[j].z, acc[j].w);
    }
}

// ------------------- K3: histogram by receiver -------------------
__global__ void k_hist(const int* __restrict__ ei, int n_edges, int n_nodes) {
    int e = blockIdx.x * blockDim.x + threadIdx.x;
    if (e >= n_edges) return;
    int r = ei[n_edges + e];
    if ((unsigned)r < (unsigned)n_nodes) atomicAdd(&g_cnt[r], 1);
}

// ------------------- K4: single-block exclusive scan -------------------
__global__ void k_scan(int n) {
    __shared__ int part[1024];
    int t = threadIdx.x;
    int chunk = (n + 1023) >> 10;
    int b = t * chunk;
    int e = min(b + chunk, n);
    int s = 0;
    for (int i = b; i < e; i++) s += g_cnt[i];
    part[t] = s;
    __syncthreads();
    for (int d = 1; d < 1024; d <<= 1) {
        int v = (t >= d) ? part[t - d] : 0;
        __syncthreads();
        part[t] += v;
        __syncthreads();
    }
    int run = (t > 0) ? part[t - 1] : 0;
    for (int i = b; i < e; i++) {
        g_off[i] = run;
        g_cur[i] = run;
        run += g_cnt[i];
    }
    if (e == n) g_off[n] = run;
}

// ------------------- K5: scatter edges into CSR order -------------------
__global__ void k_sort(const int* __restrict__ ei,
                       const float* __restrict__ elen,
                       int n_edges, int n_nodes) {
    int e = blockIdx.x * blockDim.x + threadIdx.x;
    if (e >= n_edges) return;
    int s = ei[e], r = ei[n_edges + e];
    if ((unsigned)s >= (unsigned)n_nodes || (unsigned)r >= (unsigned)n_nodes) return;
    int pos = atomicAdd(&g_cur[r], 1);
    g_ss[pos] = s;
    g_sl[pos] = elen[e];
}

// ------------------- K6: per-receiver softmax + aggregate (warp per node) -------------------
__global__ void __launch_bounds__(256) k_main(const float* __restrict__ rdls,
                                              const float* __restrict__ rtb,
                                              const float* __restrict__ rtw,
                                              const float* __restrict__ mixb,
                                              const float* __restrict__ mixs,
                                              int n_nodes) {
    int r = (blockIdx.x * blockDim.x + threadIdx.x) >> 5;
    int lane = threadIdx.x & 31;
    if (r >= n_nodes) return;
    int beg = g_off[r], end = g_off[r + 1];

    float2* aggp = (float2*)g_agg;
    if (beg == end) {
        aggp[r * 32 + lane] = make_float2(0.0f, 0.0f);
        return;
    }

    float dist_scale = softplus_f(rdls[0]);
    float4 tb = *(const float4*)rtb;
    float4 tw = *(const float4*)rtw;
    float4 mb = *(const float4*)mixb;
    float4 ms = *(const float4*)mixs;
    float4 srr = *(const float4*)&g_srad[r * 4];
    float4 str = *(const float4*)&g_stan[r * 4];

    const float NEG = __int_as_float(0xff800000);
    float mr0 = NEG, mr1 = NEG, mr2 = NEG, mr3 = NEG;
    float mt0 = NEG, mt1 = NEG, mt2 = NEG, mt3 = NEG;

    // ---- pass A: compute + STORE logits, take per-head max ----
    for (int i = beg + lane; i < end; i += 32) {
        int s = g_ss[i];
        float len = g_sl[i];
        float4 ss = *(const float4*)&g_srad[s * 4];
        float4 ts = *(const float4*)&g_stan[s * 4];
        float c = dist_scale * len;
        float t0 = softplus_f(tb.x + tw.x * len) + 1e-4f;
        float t1 = softplus_f(tb.y + tw.y * len) + 1e-4f;
        float t2 = softplus_f(tb.z + tw.z * len) + 1e-4f;
        float t3 = softplus_f(tb.w + tw.w * len) + 1e-4f;
        float4 rl, tl;
        rl.x = (ss.x - srr.x - c) / t0;
        rl.y = (ss.y - srr.y - c) / t1;
        rl.z = (ss.z - srr.z - c) / t2;
        rl.w = (ss.w - srr.w - c) / t3;
        tl.x = ts.x - str.x;
        tl.y = ts.y - str.y;
        tl.z = ts.z - str.z;
        tl.w = ts.w - str.w;
        g_er[i] = rl;
        g_et[i] = tl;
        mr0 = fmaxf(mr0, rl.x); mr1 = fmaxf(mr1, rl.y);
        mr2 = fmaxf(mr2, rl.z); mr3 = fmaxf(mr3, rl.w);
        mt0 = fmaxf(mt0, tl.x); mt1 = fmaxf(mt1, tl.y);
        mt2 = fmaxf(mt2, tl.z); mt3 = fmaxf(mt3, tl.w);
    }
    mr0 = wred_max(mr0); mr1 = wred_max(mr1); mr2 = wred_max(mr2); mr3 = wred_max(mr3);
    mt0 = wred_max(mt0); mt1 = wred_max(mt1); mt2 = wred_max(mt2); mt3 = wred_max(mt3);

    // ---- pass B: exps (from stored logits) + denominators ----
    float dr0 = 0, dr1 = 0, dr2 = 0, dr3 = 0;
    float dt0 = 0, dt1 = 0, dt2 = 0, dt3 = 0;
    for (int i = beg + lane; i < end; i += 32) {
        float4 rl = g_er[i];
        float4 tl = g_et[i];
        float4 er, et;
        er.x = __expf(rl.x - mr0);
        er.y = __expf(rl.y - mr1);
        er.z = __expf(rl.z - mr2);
        er.w = __expf(rl.w - mr3);
        et.x = __expf(tl.x - mt0);
        et.y = __expf(tl.y - mt1);
        et.z = __expf(tl.z - mt2);
        et.w = __expf(tl.w - mt3);
        g_er[i] = er;
        g_et[i] = et;
        dr0 += er.x; dr1 += er.y; dr2 += er.z; dr3 += er.w;
        dt0 += et.x; dt1 += et.y; dt2 += et.z; dt3 += et.w;
    }
    dr0 = wred_sum(dr0); dr1 = wred_sum(dr1); dr2 = wred_sum(dr2); dr3 = wred_sum(dr3);
    dt0 = wred_sum(dt0); dt1 = wred_sum(dt1); dt2 = wred_sum(dt2); dt3 = wred_sum(dt3);
    dr0 = 1.0f / (dr0 + 1e-9f); dr1 = 1.0f / (dr1 + 1e-9f);
    dr2 = 1.0f / (dr2 + 1e-9f); dr3 = 1.0f / (dr3 + 1e-9f);
    dt0 = 1.0f / (dt0 + 1e-9f); dt1 = 1.0f / (dt1 + 1e-9f);
    dt2 = 1.0f / (dt2 + 1e-9f); dt3 = 1.0f / (dt3 + 1e-9f);

    // ---- pass B2: per-edge blended weights + receiver-side totals (lane-parallel) ----
    float W10 = 0, W11 = 0, W12 = 0, W13 = 0;
    float W20 = 0, W21 = 0, W22 = 0, W23 = 0;
    for (int i = beg + lane; i < end; i += 32) {
        float len = g_sl[i];
        float4 er = g_er[i];
        float4 et = g_et[i];
        float g0 = sigmoid_f(mb.x + ms.x * len);
        float g1 = sigmoid_f(mb.y + ms.y * len);
        float g2 = sigmoid_f(mb.z + ms.z * len);
        float g3 = sigmoid_f(mb.w + ms.w * len);
        float b0 = g0 * er.x * dr0 + (1.0f - g0) * et.x * dt0;
        float b1 = g1 * er.y * dr1 + (1.0f - g1) * et.y * dt1;
        float b2 = g2 * er.z * dr2 + (1.0f - g2) * et.z * dt2;
        float b3 = g3 * er.w * dr3 + (1.0f - g3) * et.w * dt3;
        float4 w1, w2;
        w1.x = b0 * g0; w2.x = b0 * (1.0f - g0);
        w1.y = b1 * g1; w2.y = b1 * (1.0f - g1);
        w1.z = b2 * g2; w2.z = b2 * (1.0f - g2);
        w1.w = b3 * g3; w2.w = b3 * (1.0f - g3);
        g_w1[i] = w1;
        g_w2[i] = w2;
        W10 += w1.x; W11 += w1.y; W12 += w1.z; W13 += w1.w;
        W20 += w2.x; W21 += w2.y; W22 += w2.z; W23 += w2.w;
    }
    W10 = wred_sum(W10); W11 = wred_sum(W11); W12 = wred_sum(W12); W13 = wred_sum(W13);
    W20 = wred_sum(W20); W21 = wred_sum(W21); W22 = wred_sum(W22); W23 = wred_sum(W23);

    // ---- pass C: gather senders, software-pipelined ----
    const uint4* Rp = (const uint4*)g_Rh;   // 16B = all 4 heads of one g-pair
    const uint4* Tp = (const uint4*)g_Th;
    float ax = 0.0f, ay = 0.0f;
    int    s_cur = g_ss[beg];
    float4 w1c   = g_w1[beg];
    float4 w2c   = g_w2[beg];
    for (int i = beg; i < end; i++) {
        uint4 rv = Rp[s_cur * 32 + lane];
        uint4 tv = Tp[s_cur * 32 + lane];
        if (i + 1 < end) {                 // prefetch next edge metadata
            s_cur = g_ss[i + 1];
        }
        float4 w1 = w1c, w2 = w2c;
        if (i + 1 < end) {
            w1c = g_w1[i + 1];
            w2c = g_w2[i + 1];
        }
        const __half2* rh = (const __half2*)&rv;
        const __half2* th = (const __half2*)&tv;
        float2 r0 = __half22float2(rh[0]), r1 = __half22float2(rh[1]);
        float2 r2 = __half22float2(rh[2]), r3 = __half22float2(rh[3]);
        float2 t0 = __half22float2(th[0]), t1 = __half22float2(th[1]);
        float2 t2 = __half22float2(th[2]), t3 = __half22float2(th[3]);
        ax += w1.x * r0.x + w2.x * t0.x + w1.y * r1.x + w2.y * t1.x
            + w1.z * r2.x + w2.z * t2.x + w1.w * r3.x + w2.w * t3.x;
        ay += w1.x * r0.y + w2.x * t0.y + w1.y * r1.y + w2.y * t1.y
            + w1.z * r2.y + w2.z * t2.y + w1.w * r3.y + w2.w * t3.y;
    }
    // subtract factored receiver part
    {
        uint4 rv = Rp[r * 32 + lane];
        uint4 tv = Tp[r * 32 + lane];
        const __half2* rh = (const __half2*)&rv;
        const __half2* th = (const __half2*)&tv;
        float2 r0 = __half22float2(rh[0]), r1 = __half22float2(rh[1]);
        float2 r2 = __half22float2(rh[2]), r3 = __half22float2(rh[3]);
        float2 t0 = __half22float2(th[0]), t1 = __half22float2(th[1]);
        float2 t2 = __half22float2(th[2]), t3 = __half22float2(th[3]);
        ax -= W10 * r0.x + W20 * t0.x + W11 * r1.x + W21 * t1.x
            + W12 * r2.x + W22 * t2.x + W13 * r3.x + W23 * t3.x;
        ay -= W10 * r0.y + W20 * t0.y + W11 * r1.y + W21 * t1.y
            + W12 * r2.y + W22 * t2.y + W13 * r3.y + W23 * t3.y;
    }
    aggp[r * 32 + lane] = make_float2(ax * 0.25f, ay * 0.25f);
}

// ------------------- K7: out = x + agg @ w_out -------------------
#define ONB 4
__global__ void k_out(const float* __restrict__ x,
                      const float* __restrict__ w_out,
                      float* __restrict__ out,
                      int n_nodes) {
    __shared__ float sw[F * F];
    __shared__ float ag[ONB * F];
    int tid = threadIdx.x;
    for (int i = tid; i < F * F; i += 256) sw[i] = w_out[i];
    int nl = tid >> 6, g = tid & 63;
    int n = blockIdx.x * ONB + nl;
    if (n < n_nodes) ag[nl * F + g] = g_agg[n * F + g];
    __syncthreads();
    if (n >= n_nodes) return;
    float acc = x[n * F + g];
#pragma unroll
    for (int f = 0; f < F; f++) acc += ag[nl * F + f] * sw[f * F + g];
    out[n * F + g] = acc;
}

// ------------------- launch -------------------
extern "C" void kernel_launch(void* const* d_in, const int* in_sizes, int n_in,
                              void* d_out, int out_size) {
    const float* x     = (const float*)d_in[0];
    const int*   ei    = (const int*)d_in[1];     // edge_index staged as int32, [2, E]
    // d_in[2] = edge_vec (unused by reference)
    const float* elen  = (const float*)d_in[3];
    const float* wprj  = (const float*)d_in[4];
    const float* wrad  = (const float*)d_in[5];
    const float* wtan  = (const float*)d_in[6];
    const float* rsc   = (const float*)d_in[7];
    const float* tsc   = (const float*)d_in[8];
    const float* rdls  = (const float*)d_in[9];
    const float* rtb   = (const float*)d_in[10];
    const float* rtw   = (const float*)d_in[11];
    const float* mixb  = (const float*)d_in[12];
    const float* mixs  = (const float*)d_in[13];
    const float* wout  = (const float*)d_in[14];
    float*       out   = (float*)d_out;

    int n_nodes = in_sizes[0] / F;
    int n_edges = in_sizes[3];

    k_zero<<<(n_nodes + 255) / 256, 256>>>(n_nodes);
    k_vec<<<1, H * F>>>(wprj, rsc, tsc);
    k_scal<<<(n_nodes * H + 255) / 256, 256>>>(x, n_nodes);

    k_proj<<<(n_nodes + NPB - 1) / NPB, 512>>>(x, wrad, wtan, n_nodes);

    k_hist<<<(n_edges + 255) / 256, 256>>>(ei, n_edges, n_nodes);
    k_scan<<<1, 1024>>>(n_nodes);
    k_sort<<<(n_edges + 255) / 256, 256>>>(ei, elen, n_edges, n_nodes);

    k_main<<<(n_nodes * 32 + 255) / 256, 256>>>(rdls, rtb, rtw, mixb, mixs, n_nodes);
    k_out<<<(n_nodes + ONB - 1) / ONB, 256>>>(x, wout, out, n_nodes);
}

// round 12
// speedup vs baseline: 1.0976x; 1.0180x over previous
#include <cuda_runtime.h>
#include <cuda_bf16.h>
#include <cuda_fp16.h>
#include <cstdint>

#define NMAX 20000
#define NPAD 20032          // padded to 64-node blocks for k_post
#define EMAX 320000
#define F 64
#define H 4

// ------------------- scratch (static device globals; no allocation) -------------------
__device__ float   g_srad[NMAX * H];      // [n][h]
__device__ float   g_stan[NMAX * H];
__device__ float   g_vrad[H * F];         // w_proj @ radial_score
__device__ float   g_vtan[H * F];
__device__ float   g_A[NPAD * 512];       // per-receiver weighted-x sums [n][mat*256+h*64+f]
__device__ float   g_M[512 * 64];         // combined (1/4)·w_{mat,h} @ w_out

// CSR sort scratch
__device__ int     g_cnt[NMAX];
__device__ int     g_off[NMAX + 1];
__device__ int     g_cur[NMAX];
__device__ int     g_ss[EMAX];            // sorted sender
__device__ float   g_sl[EMAX];            // sorted edge_len
__device__ float4  g_er[EMAX];            // pass A: radial logits; pass B: exps
__device__ float4  g_et[EMAX];            // pass A: tangential logits; pass B: exps
__device__ float4  g_w1[EMAX];            // per-edge blended weights (radial side)
__device__ float4  g_w2[EMAX];            // per-edge blended weights (tangential side)

// ------------------- helpers -------------------
__device__ __forceinline__ float softplus_f(float v) {
    return (v > 20.0f) ? v : log1pf(__expf(v));
}
__device__ __forceinline__ float sigmoid_f(float v) {
    return 1.0f / (1.0f + __expf(-v));
}
__device__ __forceinline__ float wred_max(float v) {
#pragma unroll
    for (int d = 16; d; d >>= 1) v = fmaxf(v, __shfl_xor_sync(0xffffffffu, v, d));
    return v;
}
__device__ __forceinline__ float wred_sum(float v) {
#pragma unroll
    for (int d = 16; d; d >>= 1) v += __shfl_xor_sync(0xffffffffu, v, d);
    return v;
}

// ------------------- K0: zero counters -------------------
__global__ void k_zero(int n) {
    int i = blockIdx.x * blockDim.x + threadIdx.x;
    if (i < n) g_cnt[i] = 0;
}

// ------------------- Kp: combined matrix M = (1/4) w_{mat,h} @ w_out ----------
// grid 8 blocks = (mat,h); M[k][go], k = mat*256 + h*64 + f
__global__ void k_prep(const float* __restrict__ wrad,
                       const float* __restrict__ wtan,
                       const float* __restrict__ wout) {
    int mat = blockIdx.x >> 2, h = blockIdx.x & 3;
    const float* w = (mat ? wtan : wrad) + h * F * F;
    __shared__ float sw[F * F];
    __shared__ float so[F * F];
    int tid = threadIdx.x;
    for (int i = tid; i < F * F; i += 256) {
        sw[i] = w[i];
        so[i] = wout[i];
    }
    __syncthreads();
    for (int idx = tid; idx < F * F; idx += 256) {
        int f = idx >> 6, go = idx & 63;
        float s = 0.0f;
#pragma unroll
        for (int g = 0; g < F; g++) s += sw[f * F + g] * so[g * F + go];
        g_M[((mat * 256) + h * 64 + f) * 64 + go] = 0.25f * s;
    }
}

// ------------------- K1: score vectors v = W_proj @ score -------------------
__global__ void k_vec(const float* __restrict__ w_proj,
                      const float* __restrict__ rscore,
                      const float* __restrict__ tscore) {
    int tid = threadIdx.x;          // tid = h*64 + f
    int h = tid >> 6;
    const float* wp = w_proj + tid * F;   // w_proj[h][f][:]
    float a = 0.0f, b = 0.0f;
#pragma unroll
    for (int g = 0; g < F; g++) {
        float w = wp[g];
        a += w * rscore[h * F + g];
        b += w * tscore[h * F + g];
    }
    g_vrad[tid] = a;
    g_vtan[tid] = b;
}

// ------------------- K1b: node scalars (fp32) -------------------
__global__ void k_scal(const float* __restrict__ x, int n_nodes) {
    int t = blockIdx.x * blockDim.x + threadIdx.x;
    int n = t >> 2, h = t & 3;
    if (n >= n_nodes) return;
    const float* xr = x + n * F;
    const float* vr = g_vrad + h * F;
    const float* vt = g_vtan + h * F;
    float a = 0.0f, b = 0.0f;
#pragma unroll
    for (int f = 0; f < F; f++) {
        float xv = xr[f];
        a += xv * vr[f];
        b += xv * vt[f];
    }
    g_srad[n * H + h] = a;
    g_stan[n * H + h] = b;
}

// ------------------- K3: histogram by receiver -------------------
__global__ void k_hist(const int* __restrict__ ei, int n_edges, int n_nodes) {
    int e = blockIdx.x * blockDim.x + threadIdx.x;
    if (e >= n_edges) return;
    int r = ei[n_edges + e];
    if ((unsigned)r < (unsigned)n_nodes) atomicAdd(&g_cnt[r], 1);
}

// ------------------- K4: single-block exclusive scan -------------------
__global__ void k_scan(int n) {
    __shared__ int part[1024];
    int t = threadIdx.x;
    int chunk = (n + 1023) >> 10;
    int b = t * chunk;
    int e = min(b + chunk, n);
    int s = 0;
    for (int i = b; i < e; i++) s += g_cnt[i];
    part[t] = s;
    __syncthreads();
    for (int d = 1; d < 1024; d <<= 1) {
        int v = (t >= d) ? part[t - d] : 0;
        __syncthreads();
        part[t] += v;
        __syncthreads();
    }
    int run = (t > 0) ? part[t - 1] : 0;
    for (int i = b; i < e; i++) {
        g_off[i] = run;
        g_cur[i] = run;
        run += g_cnt[i];
    }
    if (e == n) g_off[n] = run;
}

// ------------------- K5: scatter edges into CSR order -------------------
__global__ void k_sort(const int* __restrict__ ei,
                       const float* __restrict__ elen,
                       int n_edges, int n_nodes) {
    int e = blockIdx.x * blockDim.x + threadIdx.x;
    if (e >= n_edges) return;
    int s = ei[e], r = ei[n_edges + e];
    if ((unsigned)s >= (unsigned)n_nodes || (unsigned)r >= (unsigned)n_nodes) return;
    int pos = atomicAdd(&g_cur[r], 1);
    g_ss[pos] = s;
    g_sl[pos] = elen[e];
}

// ------------------- K6: per-receiver softmax + weighted-x aggregation ---------
// warp per receiver; pass C gathers raw x[s] (256B/edge) into 8 per-head sums.
__global__ void __launch_bounds__(256) k_main(const float* __restrict__ xp,
                                              const float* __restrict__ rdls,
                                              const float* __restrict__ rtb,
                                              const float* __restrict__ rtw,
                                              const float* __restrict__ mixb,
                                              const float* __restrict__ mixs,
                                              int n_nodes) {
    int r = (blockIdx.x * blockDim.x + threadIdx.x) >> 5;
    int lane = threadIdx.x & 31;
    if (r >= n_nodes) return;
    int beg = g_off[r], end = g_off[r + 1];

    // A row for this receiver, float2 view: index = mat*128 + h*32 + lane
    float2* Ar = (float2*)&g_A[r * 512];

    if (beg == end) {
        float2 z = make_float2(0.0f, 0.0f);
#pragma unroll
        for (int c = 0; c < 8; c++) Ar[c * 32 + lane] = z;
        return;
    }

    float dist_scale = softplus_f(rdls[0]);
    float4 tb = *(const float4*)rtb;
    float4 tw = *(const float4*)rtw;
    float4 mb = *(const float4*)mixb;
    float4 ms = *(const float4*)mixs;
    float4 srr = *(const float4*)&g_srad[r * 4];
    float4 str = *(const float4*)&g_stan[r * 4];

    const float NEG = __int_as_float(0xff800000);
    float mr0 = NEG, mr1 = NEG, mr2 = NEG, mr3 = NEG;
    float mt0 = NEG, mt1 = NEG, mt2 = NEG, mt3 = NEG;

    // ---- pass A: compute + STORE logits, take per-head max ----
    for (int i = beg + lane; i < end; i += 32) {
        int s = g_ss[i];
        float len = g_sl[i];
        float4 ss = *(const float4*)&g_srad[s * 4];
        float4 ts = *(const float4*)&g_stan[s * 4];
        float c = dist_scale * len;
        float t0 = softplus_f(tb.x + tw.x * len) + 1e-4f;
        float t1 = softplus_f(tb.y + tw.y * len) + 1e-4f;
        float t2 = softplus_f(tb.z + tw.z * len) + 1e-4f;
        float t3 = softplus_f(tb.w + tw.w * len) + 1e-4f;
        float4 rl, tl;
        rl.x = (ss.x - srr.x - c) / t0;
        rl.y = (ss.y - srr.y - c) / t1;
        rl.z = (ss.z - srr.z - c) / t2;
        rl.w = (ss.w - srr.w - c) / t3;
        tl.x = ts.x - str.x;
        tl.y = ts.y - str.y;
        tl.z = ts.z - str.z;
        tl.w = ts.w - str.w;
        g_er[i] = rl;
        g_et[i] = tl;
        mr0 = fmaxf(mr0, rl.x); mr1 = fmaxf(mr1, rl.y);
        mr2 = fmaxf(mr2, rl.z); mr3 = fmaxf(mr3, rl.w);
        mt0 = fmaxf(mt0, tl.x); mt1 = fmaxf(mt1, tl.y);
        mt2 = fmaxf(mt2, tl.z); mt3 = fmaxf(mt3, tl.w);
    }
    mr0 = wred_max(mr0); mr1 = wred_max(mr1); mr2 = wred_max(mr2); mr3 = wred_max(mr3);
    mt0 = wred_max(mt0); mt1 = wred_max(mt1); mt2 = wred_max(mt2); mt3 = wred_max(mt3);

    // ---- pass B: exps (from stored logits) + denominators ----
    float dr0 = 0, dr1 = 0, dr2 = 0, dr3 = 0;
    float dt0 = 0, dt1 = 0, dt2 = 0, dt3 = 0;
    for (int i = beg + lane; i < end; i += 32) {
        float4 rl = g_er[i];
        float4 tl = g_et[i];
        float4 er, et;
        er.x = __expf(rl.x - mr0);
        er.y = __expf(rl.y - mr1);
        er.z = __expf(rl.z - mr2);
        er.w = __expf(rl.w - mr3);
        et.x = __expf(tl.x - mt0);
        et.y = __expf(tl.y - mt1);
        et.z = __expf(tl.z - mt2);
        et.w = __expf(tl.w - mt3);
        g_er[i] = er;
        g_et[i] = et;
        dr0 += er.x; dr1 += er.y; dr2 += er.z; dr3 += er.w;
        dt0 += et.x; dt1 += et.y; dt2 += et.z; dt3 += et.w;
    }
    dr0 = wred_sum(dr0); dr1 = wred_sum(dr1); dr2 = wred_sum(dr2); dr3 = wred_sum(dr3);
    dt0 = wred_sum(dt0); dt1 = wred_sum(dt1); dt2 = wred_sum(dt2); dt3 = wred_sum(dt3);
    dr0 = 1.0f / (dr0 + 1e-9f); dr1 = 1.0f / (dr1 + 1e-9f);
    dr2 = 1.0f / (dr2 + 1e-9f); dr3 = 1.0f / (dr3 + 1e-9f);
    dt0 = 1.0f / (dt0 + 1e-9f); dt1 = 1.0f / (dt1 + 1e-9f);
    dt2 = 1.0f / (dt2 + 1e-9f); dt3 = 1.0f / (dt3 + 1e-9f);

    // ---- pass B2: per-edge blended weights + receiver-side totals (lane-parallel) ----
    float W10 = 0, W11 = 0, W12 = 0, W13 = 0;
    float W20 = 0, W21 = 0, W22 = 0, W23 = 0;
    for (int i = beg + lane; i < end; i += 32) {
        float len = g_sl[i];
        float4 er = g_er[i];
        float4 et = g_et[i];
        float g0 = sigmoid_f(mb.x + ms.x * len);
        float g1 = sigmoid_f(mb.y + ms.y * len);
        float g2 = sigmoid_f(mb.z + ms.z * len);
        float g3 = sigmoid_f(mb.w + ms.w * len);
        float b0 = g0 * er.x * dr0 + (1.0f - g0) * et.x * dt0;
        float b1 = g1 * er.y * dr1 + (1.0f - g1) * et.y * dt1;
        float b2 = g2 * er.z * dr2 + (1.0f - g2) * et.z * dt2;
        float b3 = g3 * er.w * dr3 + (1.0f - g3) * et.w * dt3;
        float4 w1, w2;
        w1.x = b0 * g0; w2.x = b0 * (1.0f - g0);
        w1.y = b1 * g1; w2.y = b1 * (1.0f - g1);
        w1.z = b2 * g2; w2.z = b2 * (1.0f - g2);
        w1.w = b3 * g3; w2.w = b3 * (1.0f - g3);
        g_w1[i] = w1;
        g_w2[i] = w2;
        W10 += w1.x; W11 += w1.y; W12 += w1.z; W13 += w1.w;
        W20 += w2.x; W21 += w2.y; W22 += w2.z; W23 += w2.w;
    }
    W10 = wred_sum(W10); W11 = wred_sum(W11); W12 = wred_sum(W12); W13 = wred_sum(W13);
    W20 = wred_sum(W20); W21 = wred_sum(W21); W22 = wred_sum(W22); W23 = wred_sum(W23);

    // ---- pass C: gather raw x[s], accumulate 8 weighted sums (pipelined) ----
    const float2* Xp = (const float2*)xp;   // x[n][64] -> 32 float2/node; lane owns pair
    float2 a10 = {0,0}, a11 = {0,0}, a12 = {0,0}, a13 = {0,0};
    float2 a20 = {0,0}, a21 = {0,0}, a22 = {0,0}, a23 = {0,0};
    int    s_cur = g_ss[beg];
    float4 w1c   = g_w1[beg];
    float4 w2c   = g_w2[beg];
    for (int i = beg; i < end; i++) {
        float2 xv = Xp[s_cur * 32 + lane];
        if (i + 1 < end) s_cur = g_ss[i + 1];
        float4 w1 = w1c, w2 = w2c;
        if (i + 1 < end) { w1c = g_w1[i + 1]; w2c = g_w2[i + 1]; }
        a10.x += w1.x * xv.x; a10.y += w1.x * xv.y;
        a11.x += w1.y * xv.x; a11.y += w1.y * xv.y;
        a12.x += w1.z * xv.x; a12.y += w1.z * xv.y;
        a13.x += w1.w * xv.x; a13.y += w1.w * xv.y;
        a20.x += w2.x * xv.x; a20.y += w2.x * xv.y;
        a21.x += w2.y * xv.x; a21.y += w2.y * xv.y;
        a22.x += w2.z * xv.x; a22.y += w2.z * xv.y;
        a23.x += w2.w * xv.x; a23.y += w2.w * xv.y;
    }
    // receiver correction: A -= W_total * x[r]
    {
        float2 xr = Xp[r * 32 + lane];
        a10.x -= W10 * xr.x; a10.y -= W10 * xr.y;
        a11.x -= W11 * xr.x; a11.y -= W11 * xr.y;
        a12.x -= W12 * xr.x; a12.y -= W12 * xr.y;
        a13.x -= W13 * xr.x; a13.y -= W13 * xr.y;
        a20.x -= W20 * xr.x; a20.y -= W20 * xr.y;
        a21.x -= W21 * xr.x; a21.y -= W21 * xr.y;
        a22.x -= W22 * xr.x; a22.y -= W22 * xr.y;
        a23.x -= W23 * xr.x; a23.y -= W23 * xr.y;
    }
    Ar[0 * 32 + lane] = a10;   // mat=0 (radial), h=0..3
    Ar[1 * 32 + lane] = a11;
    Ar[2 * 32 + lane] = a12;
    Ar[3 * 32 + lane] = a13;
    Ar[4 * 32 + lane] = a20;   // mat=1 (tangential)
    Ar[5 * 32 + lane] = a21;
    Ar[6 * 32 + lane] = a22;
    Ar[7 * 32 + lane] = a23;
}

// ------------------- K7: out = x + A @ M  (fused proj + head-mean + w_out) ----
#define PNB 64
__global__ void __launch_bounds__(256) k_post(const float* __restrict__ x,
                                              float* __restrict__ out,
                                              int n_nodes) {
    int tid = threadIdx.x;
    int ng  = tid >> 4;          // 16 node-groups of 4
    int goq = tid & 15;          // 4 output columns
    int n0 = blockIdx.x * PNB + ng * 4;

    const float4* Mp = (const float4*)g_M;    // row k: 16 float4
    float4 acc0 = {0,0,0,0}, acc1 = {0,0,0,0}, acc2 = {0,0,0,0}, acc3 = {0,0,0,0};

    const float* A0 = &g_A[(size_t)n0 * 512];

#pragma unroll 2
    for (int k = 0; k < 512; k += 4) {
        float4 m0 = Mp[(k + 0) * 16 + goq];
        float4 m1 = Mp[(k + 1) * 16 + goq];
        float4 m2 = Mp[(k + 2) * 16 + goq];
        float4 m3 = Mp[(k + 3) * 16 + goq];
        float4 a0 = *(const float4*)&A0[0 * 512 + k];
        float4 a1 = *(const float4*)&A0[1 * 512 + k];
        float4 a2 = *(const float4*)&A0[2 * 512 + k];
        float4 a3 = *(const float4*)&A0[3 * 512 + k];
        acc0.x += a0.x * m0.x + a0.y * m1.x + a0.z * m2.x + a0.w * m3.x;
        acc0.y += a0.x * m0.y + a0.y * m1.y + a0.z * m2.y + a0.w * m3.y;
        acc0.z += a0.x * m0.z + a0.y * m1.z + a0.z * m2.z + a0.w * m3.z;
        acc0.w += a0.x * m0.w + a0.y * m1.w + a0.z * m2.w + a0.w * m3.w;
        acc1.x += a1.x * m0.x + a1.y * m1.x + a1.z * m2.x + a1.w * m3.x;
        acc1.y += a1.x * m0.y + a1.y * m1.y + a1.z * m2.y + a1.w * m3.y;
        acc1.z += a1.x * m0.z + a1.y * m1.z + a1.z * m2.z + a1.w * m3.z;
        acc1.w += a1.x * m0.w + a1.y * m1.w + a1.z * m2.w + a1.w * m3.w;
        acc2.x += a2.x * m0.x + a2.y * m1.x + a2.z * m2.x + a2.w * m3.x;
        acc2.y += a2.x * m0.y + a2.y * m1.y + a2.z * m2.y + a2.w * m3.y;
        acc2.z += a2.x * m0.z + a2.y * m1.z + a2.z * m2.z + a2.w * m3.z;
        acc2.w += a2.x * m0.w + a2.y * m1.w + a2.z * m2.w + a2.w * m3.w;
        acc3.x += a3.x * m0.x + a3.y * m1.x + a3.z * m2.x + a3.w * m3.x;
        acc3.y += a3.x * m0.y + a3.y * m1.y + a3.z * m2.y + a3.w * m3.y;
        acc3.z += a3.x * m0.z + a3.y * m1.z + a3.z * m2.z + a3.w * m3.z;
        acc3.w += a3.x * m0.w + a3.y * m1.w + a3.z * m2.w + a3.w * m3.w;
    }

    float4 accs[4] = {acc0, acc1, acc2, acc3};
#pragma unroll
    for (int j = 0; j < 4; j++) {
        int n = n0 + j;
        if (n >= n_nodes) break;
        float4 xv = *(const float4*)&x[n * F + goq * 4];
        float4 o;
        o.x = xv.x + accs[j].x;
        o.y = xv.y + accs[j].y;
        o.z = xv.z + accs[j].z;
        o.w = xv.w + accs[j].w;
        *(float4*)&out[n * F + goq * 4] = o;
    }
}

// ------------------- launch -------------------
extern "C" void kernel_launch(void* const* d_in, const int* in_sizes, int n_in,
                              void* d_out, int out_size) {
    const float* x     = (const float*)d_in[0];
    const int*   ei    = (const int*)d_in[1];     // edge_index staged as int32, [2, E]
    // d_in[2] = edge_vec (unused by reference)
    const float* elen  = (const float*)d_in[3];
    const float* wprj  = (const float*)d_in[4];
    const float* wrad  = (const float*)d_in[5];
    const float* wtan  = (const float*)d_in[6];
    const float* rsc   = (const float*)d_in[7];
    const float* tsc   = (const float*)d_in[8];
    const float* rdls  = (const float*)d_in[9];
    const float* rtb   = (const float*)d_in[10];
    const float* rtw   = (const float*)d_in[11];
    const float* mixb  = (const float*)d_in[12];
    const float* mixs  = (const float*)d_in[13];
    const float* wout  = (const float*)d_in[14];
    float*       out   = (float*)d_out;

    int n_nodes = in_sizes[0] / F;
    int n_edges = in_sizes[3];

    k_prep<<<8, 256>>>(wrad, wtan, wout);
    k_zero<<<(n_nodes + 255) / 256, 256>>>(n_nodes);
    k_vec<<<1, H * F>>>(wprj, rsc, tsc);
    k_scal<<<(n_nodes * H + 255) / 256, 256>>>(x, n_nodes);

    k_hist<<<(n_edges + 255) / 256, 256>>>(ei, n_edges, n_nodes);
    k_scan<<<1, 1024>>>(n_nodes);
    k_sort<<<(n_edges + 255) / 256, 256>>>(ei, elen, n_edges, n_nodes);

    k_main<<<(n_nodes * 32 + 255) / 256, 256>>>(x, rdls, rtb, rtw, mixb, mixs, n_nodes);
    k_post<<<(n_nodes + PNB - 1) / PNB, 256>>>(x, out, n_nodes);
}

// round 13
// speedup vs baseline: 1.2452x; 1.1344x over previous
#include <cuda_runtime.h>
#include <cuda_bf16.h>
#include <cuda_fp16.h>
#include <cstdint>

#define NMAX 20000
#define NPAD 20032          // padded to 64-node blocks for k_post
#define EMAX 320000
#define F 64
#define H 4

// ------------------- scratch (static device globals; no allocation) -------------------
__device__ float   g_srad[NMAX * H];      // [n][h]
__device__ float   g_stan[NMAX * H];
__device__ float   g_vrad[H * F];         // w_proj @ radial_score
__device__ float   g_vtan[H * F];
__device__ float   g_A[NPAD * 512];       // per-receiver weighted-x sums [n][mat*256+h*64+f]
__device__ float   g_M[512 * 64];         // combined (1/4)·w_{mat,h} @ w_out

// CSR sort scratch
__device__ int     g_cnt[NMAX];
__device__ int     g_off[NMAX + 1];
__device__ int     g_cur[NMAX];
__device__ int     g_ss[EMAX];            // sorted sender
__device__ float   g_sl[EMAX];            // sorted edge_len
__device__ float4  g_er[EMAX];            // pass A: radial logits; pass B: exps
__device__ float4  g_et[EMAX];            // pass A: tangential logits; pass B: exps
__device__ float4  g_w1[EMAX];            // per-edge blended weights (radial side)
__device__ float4  g_w2[EMAX];            // per-edge blended weights (tangential side)

// ------------------- helpers -------------------
__device__ __forceinline__ float softplus_f(float v) {
    return (v > 20.0f) ? v : log1pf(__expf(v));
}
__device__ __forceinline__ float sigmoid_f(float v) {
    return 1.0f / (1.0f + __expf(-v));
}
__device__ __forceinline__ float wred_max(float v) {
#pragma unroll
    for (int d = 16; d; d >>= 1) v = fmaxf(v, __shfl_xor_sync(0xffffffffu, v, d));
    return v;
}
__device__ __forceinline__ float wred_sum(float v) {
#pragma unroll
    for (int d = 16; d; d >>= 1) v += __shfl_xor_sync(0xffffffffu, v, d);
    return v;
}

// ------------------- K0: fused setup (prep-M | score vectors | zero counters) --
// blocks 0..7:  M = (1/4) w_{mat,h} @ w_out   (mat = b>>2, h = b&3)
// block  8:     v = W_proj @ score
// blocks 9.. :  zero g_cnt
__global__ void k_setup(const float* __restrict__ wrad,
                        const float* __restrict__ wtan,
                        const float* __restrict__ wout,
                        const float* __restrict__ wprj,
                        const float* __restrict__ rscore,
                        const float* __restrict__ tscore,
                        int n_nodes) {
    int b = blockIdx.x;
    int tid = threadIdx.x;
    if (b < 8) {
        int mat = b >> 2, h = b & 3;
        const float* w = (mat ? wtan : wrad) + h * F * F;
        __shared__ float sw[F * F];
        __shared__ float so[F * F];
        for (int i = tid; i < F * F; i += 256) {
            sw[i] = w[i];
            so[i] = wout[i];
        }
        __syncthreads();
        for (int idx = tid; idx < F * F; idx += 256) {
            int f = idx >> 6, go = idx & 63;
            float s = 0.0f;
#pragma unroll
            for (int g = 0; g < F; g++) s += sw[f * F + g] * so[g * F + go];
            g_M[((mat * 256) + h * 64 + f) * 64 + go] = 0.25f * s;
        }
    } else if (b == 8) {
        int h = tid >> 6;                    // tid = h*64 + f
        const float* wp = wprj + tid * F;
        float a = 0.0f, c = 0.0f;
#pragma unroll
        for (int g = 0; g < F; g++) {
            float w = wp[g];
            a += w * rscore[h * F + g];
            c += w * tscore[h * F + g];
        }
        g_vrad[tid] = a;
        g_vtan[tid] = c;
    } else {
        int i = (b - 9) * 256 + tid;
        if (i < n_nodes) g_cnt[i] = 0;
    }
}

// ------------------- K1b: node scalars (smem-staged) -------------------
#define SNB 32
__global__ void __launch_bounds__(256) k_scal(const float* __restrict__ x,
                                              int n_nodes) {
    __shared__ float xs[SNB][72];   // padded: 72*4B=288B stride -> bank offset 8/row
    __shared__ float vs[8][68];     // padded: 68*4B=272B stride -> bank offset 4/row
    int tid = threadIdx.x;
    int base = blockIdx.x * SNB;

    // stage x tile (512 float4)
    for (int i = tid; i < SNB * 16; i += 256) {
        int nl = i >> 4, fq = i & 15;
        int n = base + nl;
        float4 v = (n < n_nodes) ? *(const float4*)&x[n * F + fq * 4]
                                 : make_float4(0.f, 0.f, 0.f, 0.f);
        *(float4*)&xs[nl][fq * 4] = v;
    }
    // stage score vectors (rows: mat*4 + h)
    if (tid < 128) {
        int row = tid >> 4, fq = tid & 15;
        int mat = row >> 2, h = row & 3;
        const float* src = (mat ? g_vtan : g_vrad) + h * F;
        *(float4*)&vs[row][fq * 4] = *(const float4*)&src[fq * 4];
    }
    __syncthreads();

    int nl = tid >> 3, c = tid & 7;          // c = mat*4 + h
    int mat = c >> 2, h = c & 3;
    int n = base + nl;
    if (n >= n_nodes) return;
    const float* xr = xs[nl];
    const float* vv = vs[c];
    float s = 0.0f;
#pragma unroll
    for (int fq = 0; fq < 16; fq++) {
        float4 xv = *(const float4*)&xr[fq * 4];
        float4 v4 = *(const float4*)&vv[fq * 4];
        s += xv.x * v4.x + xv.y * v4.y + xv.z * v4.z + xv.w * v4.w;
    }
    if (mat) g_stan[n * H + h] = s;
    else     g_srad[n * H + h] = s;
}

// ------------------- K3: histogram by receiver (4 edges/thread) -------------------
__global__ void k_hist(const int* __restrict__ ei, int n_edges, int n_nodes) {
    int i = blockIdx.x * blockDim.x + threadIdx.x;
    int e0 = i * 4;
    if (e0 >= n_edges) return;
    if (((n_edges & 3) == 0) && (e0 + 3 < n_edges)) {
        int4 r4 = *(const int4*)&ei[n_edges + e0];
        if ((unsigned)r4.x < (unsigned)n_nodes) atomicAdd(&g_cnt[r4.x], 1);
        if ((unsigned)r4.y < (unsigned)n_nodes) atomicAdd(&g_cnt[r4.y], 1);
        if ((unsigned)r4.z < (unsigned)n_nodes) atomicAdd(&g_cnt[r4.z], 1);
        if ((unsigned)r4.w < (unsigned)n_nodes) atomicAdd(&g_cnt[r4.w], 1);
    } else {
        int e1 = min(e0 + 4, n_edges);
        for (int e = e0; e < e1; e++) {
            int r = ei[n_edges + e];
            if ((unsigned)r < (unsigned)n_nodes) atomicAdd(&g_cnt[r], 1);
        }
    }
}

// ------------------- K4: single-block exclusive scan -------------------
__global__ void k_scan(int n) {
    __shared__ int part[1024];
    int t = threadIdx.x;
    int chunk = (n + 1023) >> 10;
    int b = t * chunk;
    int e = min(b + chunk, n);
    int s = 0;
    for (int i = b; i < e; i++) s += g_cnt[i];
    part[t] = s;
    __syncthreads();
    for (int d = 1; d < 1024; d <<= 1) {
        int v = (t >= d) ? part[t - d] : 0;
        __syncthreads();
        part[t] += v;
        __syncthreads();
    }
    int run = (t > 0) ? part[t - 1] : 0;
    for (int i = b; i < e; i++) {
        g_off[i] = run;
        g_cur[i] = run;
        run += g_cnt[i];
    }
    if (e == n) g_off[n] = run;
}

// ------------------- K5: scatter edges into CSR order (4 edges/thread) ---------
__global__ void k_sort(const int* __restrict__ ei,
                       const float* __restrict__ elen,
                       int n_edges, int n_nodes) {
    int i = blockIdx.x * blockDim.x + threadIdx.x;
    int e0 = i * 4;
    if (e0 >= n_edges) return;
    if (((n_edges & 3) == 0) && (e0 + 3 < n_edges)) {
        int4   s4 = *(const int4*)&ei[e0];
        int4   r4 = *(const int4*)&ei[n_edges + e0];
        float4 l4 = *(const float4*)&elen[e0];
        int   sa[4] = {s4.x, s4.y, s4.z, s4.w};
        int   ra[4] = {r4.x, r4.y, r4.z, r4.w};
        float la[4] = {l4.x, l4.y, l4.z, l4.w};
#pragma unroll
        for (int j = 0; j < 4; j++) {
            if ((unsigned)sa[j] >= (unsigned)n_nodes ||
                (unsigned)ra[j] >= (unsigned)n_nodes) continue;
            int pos = atomicAdd(&g_cur[ra[j]], 1);
            g_ss[pos] = sa[j];
            g_sl[pos] = la[j];
        }
    } else {
        int e1 = min(e0 + 4, n_edges);
        for (int e = e0; e < e1; e++) {
            int s = ei[e], r = ei[n_edges + e];
            if ((unsigned)s >= (unsigned)n_nodes ||
                (unsigned)r >= (unsigned)n_nodes) continue;
            int pos = atomicAdd(&g_cur[r], 1);
            g_ss[pos] = s;
            g_sl[pos] = elen[e];
        }
    }
}

// ------------------- K6: per-receiver softmax + weighted-x aggregation ---------
// warp per receiver; pass C gathers raw x[s] (256B/edge) into 8 per-head sums.
__global__ void __launch_bounds__(256) k_main(const float* __restrict__ xp,
                                              const float* __restrict__ rdls,
                                              const float* __restrict__ rtb,
                                              const float* __restrict__ rtw,
                                              const float* __restrict__ mixb,
                                              const float* __restrict__ mixs,
                                              int n_nodes) {
    int r = (blockIdx.x * blockDim.x + threadIdx.x) >> 5;
    int lane = threadIdx.x & 31;
    if (r >= n_nodes) return;
    int beg = g_off[r], end = g_off[r + 1];

    // A row for this receiver, float2 view: index = mat*128 + h*32 + lane
    float2* Ar = (float2*)&g_A[r * 512];

    if (beg == end) {
        float2 z = make_float2(0.0f, 0.0f);
#pragma unroll
        for (int c = 0; c < 8; c++) Ar[c * 32 + lane] = z;
        return;
    }

    float dist_scale = softplus_f(rdls[0]);
    float4 tb = *(const float4*)rtb;
    float4 tw = *(const float4*)rtw;
    float4 mb = *(const float4*)mixb;
    float4 ms = *(const float4*)mixs;
    float4 srr = *(const float4*)&g_srad[r * 4];
    float4 str = *(const float4*)&g_stan[r * 4];

    const float NEG = __int_as_float(0xff800000);
    float mr0 = NEG, mr1 = NEG, mr2 = NEG, mr3 = NEG;
    float mt0 = NEG, mt1 = NEG, mt2 = NEG, mt3 = NEG;

    // ---- pass A: compute + STORE logits, take per-head max ----
    for (int i = beg + lane; i < end; i += 32) {
        int s = g_ss[i];
        float len = g_sl[i];
        float4 ss = *(const float4*)&g_srad[s * 4];
        float4 ts = *(const float4*)&g_stan[s * 4];
        float c = dist_scale * len;
        float t0 = softplus_f(tb.x + tw.x * len) + 1e-4f;
        float t1 = softplus_f(tb.y + tw.y * len) + 1e-4f;
        float t2 = softplus_f(tb.z + tw.z * len) + 1e-4f;
        float t3 = softplus_f(tb.w + tw.w * len) + 1e-4f;
        float4 rl, tl;
        rl.x = (ss.x - srr.x - c) / t0;
        rl.y = (ss.y - srr.y - c) / t1;
        rl.z = (ss.z - srr.z - c) / t2;
        rl.w = (ss.w - srr.w - c) / t3;
        tl.x = ts.x - str.x;
        tl.y = ts.y - str.y;
        tl.z = ts.z - str.z;
        tl.w = ts.w - str.w;
        g_er[i] = rl;
        g_et[i] = tl;
        mr0 = fmaxf(mr0, rl.x); mr1 = fmaxf(mr1, rl.y);
        mr2 = fmaxf(mr2, rl.z); mr3 = fmaxf(mr3, rl.w);
        mt0 = fmaxf(mt0, tl.x); mt1 = fmaxf(mt1, tl.y);
        mt2 = fmaxf(mt2, tl.z); mt3 = fmaxf(mt3, tl.w);
    }
    mr0 = wred_max(mr0); mr1 = wred_max(mr1); mr2 = wred_max(mr2); mr3 = wred_max(mr3);
    mt0 = wred_max(mt0); mt1 = wred_max(mt1); mt2 = wred_max(mt2); mt3 = wred_max(mt3);

    // ---- pass B: exps (from stored logits) + denominators ----
    float dr0 = 0, dr1 = 0, dr2 = 0, dr3 = 0;
    float dt0 = 0, dt1 = 0, dt2 = 0, dt3 = 0;
    for (int i = beg + lane; i < end; i += 32) {
        float4 rl = g_er[i];
        float4 tl = g_et[i];
        float4 er, et;
        er.x = __expf(rl.x - mr0);
        er.y = __expf(rl.y - mr1);
        er.z = __expf(rl.z - mr2);
        er.w = __expf(rl.w - mr3);
        et.x = __expf(tl.x - mt0);
        et.y = __expf(tl.y - mt1);
        et.z = __expf(tl.z - mt2);
        et.w = __expf(tl.w - mt3);
        g_er[i] = er;
        g_et[i] = et;
        dr0 += er.x; dr1 += er.y; dr2 += er.z; dr3 += er.w;
        dt0 += et.x; dt1 += et.y; dt2 += et.z; dt3 += et.w;
    }
    dr0 = wred_sum(dr0); dr1 = wred_sum(dr1); dr2 = wred_sum(dr2); dr3 = wred_sum(dr3);
    dt0 = wred_sum(dt0); dt1 = wred_sum(dt1); dt2 = wred_sum(dt2); dt3 = wred_sum(dt3);
    dr0 = 1.0f / (dr0 + 1e-9f); dr1 = 1.0f / (dr1 + 1e-9f);
    dr2 = 1.0f / (dr2 + 1e-9f); dr3 = 1.0f / (dr3 + 1e-9f);
    dt0 = 1.0f / (dt0 + 1e-9f); dt1 = 1.0f / (dt1 + 1e-9f);
    dt2 = 1.0f / (dt2 + 1e-9f); dt3 = 1.0f / (dt3 + 1e-9f);

    // ---- pass B2: per-edge blended weights + receiver-side totals (lane-parallel) ----
    float W10 = 0, W11 = 0, W12 = 0, W13 = 0;
    float W20 = 0, W21 = 0, W22 = 0, W23 = 0;
    for (int i = beg + lane; i < end; i += 32) {
        float len = g_sl[i];
        float4 er = g_er[i];
        float4 et = g_et[i];
        float g0 = sigmoid_f(mb.x + ms.x * len);
        float g1 = sigmoid_f(mb.y + ms.y * len);
        float g2 = sigmoid_f(mb.z + ms.z * len);
        float g3 = sigmoid_f(mb.w + ms.w * len);
        float b0 = g0 * er.x * dr0 + (1.0f - g0) * et.x * dt0;
        float b1 = g1 * er.y * dr1 + (1.0f - g1) * et.y * dt1;
        float b2 = g2 * er.z * dr2 + (1.0f - g2) * et.z * dt2;
        float b3 = g3 * er.w * dr3 + (1.0f - g3) * et.w * dt3;
        float4 w1, w2;
        w1.x = b0 * g0; w2.x = b0 * (1.0f - g0);
        w1.y = b1 * g1; w2.y = b1 * (1.0f - g1);
        w1.z = b2 * g2; w2.z = b2 * (1.0f - g2);
        w1.w = b3 * g3; w2.w = b3 * (1.0f - g3);
        g_w1[i] = w1;
        g_w2[i] = w2;
        W10 += w1.x; W11 += w1.y; W12 += w1.z; W13 += w1.w;
        W20 += w2.x; W21 += w2.y; W22 += w2.z; W23 += w2.w;
    }
    W10 = wred_sum(W10); W11 = wred_sum(W11); W12 = wred_sum(W12); W13 = wred_sum(W13);
    W20 = wred_sum(W20); W21 = wred_sum(W21); W22 = wred_sum(W22); W23 = wred_sum(W23);

    // ---- pass C: gather raw x[s], accumulate 8 weighted sums (pipelined) ----
    const float2* Xp = (const float2*)xp;   // x[n][64] -> 32 float2/node; lane owns pair
    float2 a10 = {0,0}, a11 = {0,0}, a12 = {0,0}, a13 = {0,0};
    float2 a20 = {0,0}, a21 = {0,0}, a22 = {0,0}, a23 = {0,0};
    int    s_cur = g_ss[beg];
    float4 w1c   = g_w1[beg];
    float4 w2c   = g_w2[beg];
    for (int i = beg; i < end; i++) {
        float2 xv = Xp[s_cur * 32 + lane];
        if (i + 1 < end) s_cur = g_ss[i + 1];
        float4 w1 = w1c, w2 = w2c;
        if (i + 1 < end) { w1c = g_w1[i + 1]; w2c = g_w2[i + 1]; }
        a10.x += w1.x * xv.x; a10.y += w1.x * xv.y;
        a11.x += w1.y * xv.x; a11.y += w1.y * xv.y;
        a12.x += w1.z * xv.x; a12.y += w1.z * xv.y;
        a13.x += w1.w * xv.x; a13.y += w1.w * xv.y;
        a20.x += w2.x * xv.x; a20.y += w2.x * xv.y;
        a21.x += w2.y * xv.x; a21.y += w2.y * xv.y;
        a22.x += w2.z * xv.x; a22.y += w2.z * xv.y;
        a23.x += w2.w * xv.x; a23.y += w2.w * xv.y;
    }
    // receiver correction: A -= W_total * x[r]
    {
        float2 xr = Xp[r * 32 + lane];
        a10.x -= W10 * xr.x; a10.y -= W10 * xr.y;
        a11.x -= W11 * xr.x; a11.y -= W11 * xr.y;
        a12.x -= W12 * xr.x; a12.y -= W12 * xr.y;
        a13.x -= W13 * xr.x; a13.y -= W13 * xr.y;
        a20.x -= W20 * xr.x; a20.y -= W20 * xr.y;
        a21.x -= W21 * xr.x; a21.y -= W21 * xr.y;
        a22.x -= W22 * xr.x; a22.y -= W22 * xr.y;
        a23.x -= W23 * xr.x; a23.y -= W23 * xr.y;
    }
    Ar[0 * 32 + lane] = a10;   // mat=0 (radial), h=0..3
    Ar[1 * 32 + lane] = a11;
    Ar[2 * 32 + lane] = a12;
    Ar[3 * 32 + lane] = a13;
    Ar[4 * 32 + lane] = a20;   // mat=1 (tangential)
    Ar[5 * 32 + lane] = a21;
    Ar[6 * 32 + lane] = a22;
    Ar[7 * 32 + lane] = a23;
}

// ------------------- K7: out = x + A @ M  (fused proj + head-mean + w_out) ----
#define PNB 64
__global__ void __launch_bounds__(256) k_post(const float* __restrict__ x,
                                              float* __restrict__ out,
                                              int n_nodes) {
    int tid = threadIdx.x;
    int ng  = tid >> 4;          // 16 node-groups of 4
    int goq = tid & 15;          // 4 output columns
    int n0 = blockIdx.x * PNB + ng * 4;

    const float4* Mp = (const float4*)g_M;    // row k: 16 float4
    float4 acc0 = {0,0,0,0}, acc1 = {0,0,0,0}, acc2 = {0,0,0,0}, acc3 = {0,0,0,0};

    const float* A0 = &g_A[(size_t)n0 * 512];

#pragma unroll 2
    for (int k = 0; k < 512; k += 4) {
        float4 m0 = __ldg(&Mp[(k + 0) * 16 + goq]);
        float4 m1 = __ldg(&Mp[(k + 1) * 16 + goq]);
        float4 m2 = __ldg(&Mp[(k + 2) * 16 + goq]);
        float4 m3 = __ldg(&Mp[(k + 3) * 16 + goq]);
        float4 a0 = *(const float4*)&A0[0 * 512 + k];
        float4 a1 = *(const float4*)&A0[1 * 512 + k];
        float4 a2 = *(const float4*)&A0[2 * 512 + k];
        float4 a3 = *(const float4*)&A0[3 * 512 + k];
        acc0.x += a0.x * m0.x + a0.y * m1.x + a0.z * m2.x + a0.w * m3.x;
        acc0.y += a0.x * m0.y + a0.y * m1.y + a0.z * m2.y + a0.w * m3.y;
        acc0.z += a0.x * m0.z + a0.y * m1.z + a0.z * m2.z + a0.w * m3.z;
        acc0.w += a0.x * m0.w + a0.y * m1.w + a0.z * m2.w + a0.w * m3.w;
        acc1.x += a1.x * m0.x + a1.y * m1.x + a1.z * m2.x + a1.w * m3.x;
        acc1.y += a1.x * m0.y + a1.y * m1.y + a1.z * m2.y + a1.w * m3.y;
        acc1.z += a1.x * m0.z + a1.y * m1.z + a1.z * m2.z + a1.w * m3.z;
        acc1.w += a1.x * m0.w + a1.y * m1.w + a1.z * m2.w + a1.w * m3.w;
        acc2.x += a2.x * m0.x + a2.y * m1.x + a2.z * m2.x + a2.w * m3.x;
        acc2.y += a2.x * m0.y + a2.y * m1.y + a2.z * m2.y + a2.w * m3.y;
        acc2.z += a2.x * m0.z + a2.y * m1.z + a2.z * m2.z + a2.w * m3.z;
        acc2.w += a2.x * m0.w + a2.y * m1.w + a2.z * m2.w + a2.w * m3.w;
        acc3.x += a3.x * m0.x + a3.y * m1.x + a3.z * m2.x + a3.w * m3.x;
        acc3.y += a3.x * m0.y + a3.y * m1.y + a3.z * m2.y + a3.w * m3.y;
        acc3.z += a3.x * m0.z + a3.y * m1.z + a3.z * m2.z + a3.w * m3.z;
        acc3.w += a3.x * m0.w + a3.y * m1.w + a3.z * m2.w + a3.w * m3.w;
    }

    float4 accs[4] = {acc0, acc1, acc2, acc3};
#pragma unroll
    for (int j = 0; j < 4; j++) {
        int n = n0 + j;
        if (n >= n_nodes) break;
        float4 xv = *(const float4*)&x[n * F + goq * 4];
        float4 o;
        o.x = xv.x + accs[j].x;
        o.y = xv.y + accs[j].y;
        o.z = xv.z + accs[j].z;
        o.w = xv.w + accs[j].w;
        *(float4*)&out[n * F + goq * 4] = o;
    }
}

// ------------------- launch -------------------
extern "C" void kernel_launch(void* const* d_in, const int* in_sizes, int n_in,
                              void* d_out, int out_size) {
    const float* x     = (const float*)d_in[0];
    const int*   ei    = (const int*)d_in[1];     // edge_index staged as int32, [2, E]
    // d_in[2] = edge_vec (unused by reference)
    const float* elen  = (const float*)d_in[3];
    const float* wprj  = (const float*)d_in[4];
    const float* wrad  = (const float*)d_in[5];
    const float* wtan  = (const float*)d_in[6];
    const float* rsc   = (const float*)d_in[7];
    const float* tsc   = (const float*)d_in[8];
    const float* rdls  = (const float*)d_in[9];
    const float* rtb   = (const float*)d_in[10];
    const float* rtw   = (const float*)d_in[11];
    const float* mixb  = (const float*)d_in[12];
    const float* mixs  = (const float*)d_in[13];
    const float* wout  = (const float*)d_in[14];
    float*       out   = (float*)d_out;

    int n_nodes = in_sizes[0] / F;
    int n_edges = in_sizes[3];

    k_setup<<<9 + (n_nodes + 255) / 256, 256>>>(wrad, wtan, wout,
                                                wprj, rsc, tsc, n_nodes);
    k_scal<<<(n_nodes + SNB - 1) / SNB, 256>>>(x, n_nodes);

    int ethreads = (n_edges + 3) / 4;
    k_hist<<<(ethreads + 255) / 256, 256>>>(ei, n_edges, n_nodes);
    k_scan<<<1, 1024>>>(n_nodes);
    k_sort<<<(ethreads + 255) / 256, 256>>>(ei, elen, n_edges, n_nodes);

    k_main<<<(n_nodes * 32 + 255) / 256, 256>>>(x, rdls, rtb, rtw, mixb, mixs, n_nodes);
    k_post<<<(n_nodes + PNB - 1) / PNB, 256>>>(x, out, n_nodes);
}

// round 14
// speedup vs baseline: 1.4405x; 1.1569x over previous
#include <cuda_runtime.h>
#include <cuda_bf16.h>
#include <cuda_fp16.h>
#include <cstdint>

#define NMAX 20000
#define NPAD 20032          // padded to 64-node blocks for k_post
#define EMAX 320000
#define F 64
#define H 4
#define SCB 1024            // elements per scan block

// ------------------- scratch (static device globals; no allocation) -------------------
__device__ float   g_srad[NMAX * H];      // [n][h]
__device__ float   g_stan[NMAX * H];
__device__ float   g_vrad[H * F];         // w_proj @ radial_score
__device__ float   g_vtan[H * F];
__device__ float   g_A[NPAD * 512];       // per-receiver weighted-x sums [n][mat*256+h*64+f]
__device__ float   g_M[512 * 64];         // combined (1/4)·w_{mat,h} @ w_out

// CSR sort scratch
__device__ int     g_cnt[NMAX];
__device__ int     g_off[NMAX + 1];
__device__ int     g_cur[NMAX];
__device__ int     g_bsum[64];            // per-scan-block totals
__device__ int     g_ss[EMAX];            // sorted sender
__device__ float   g_sl[EMAX];            // sorted edge_len
__device__ float4  g_er[EMAX];            // pass A: radial logits; pass B: exps
__device__ float4  g_et[EMAX];            // pass A: tangential logits; pass B: exps
__device__ float4  g_w1[EMAX];            // per-edge blended weights (radial side)
__device__ float4  g_w2[EMAX];            // per-edge blended weights (tangential side)

// ------------------- helpers -------------------
__device__ __forceinline__ float softplus_f(float v) {
    return (v > 20.0f) ? v : log1pf(__expf(v));
}
__device__ __forceinline__ float sigmoid_f(float v) {
    return 1.0f / (1.0f + __expf(-v));
}
__device__ __forceinline__ float wred_max(float v) {
#pragma unroll
    for (int d = 16; d; d >>= 1) v = fmaxf(v, __shfl_xor_sync(0xffffffffu, v, d));
    return v;
}
__device__ __forceinline__ float wred_sum(float v) {
#pragma unroll
    for (int d = 16; d; d >>= 1) v += __shfl_xor_sync(0xffffffffu, v, d);
    return v;
}

// ------------------- K0: fused setup (prep-M | score vectors | zero counters) --
__global__ void k_setup(const float* __restrict__ wrad,
                        const float* __restrict__ wtan,
                        const float* __restrict__ wout,
                        const float* __restrict__ wprj,
                        const float* __restrict__ rscore,
                        const float* __restrict__ tscore,
                        int n_nodes) {
    int b = blockIdx.x;
    int tid = threadIdx.x;
    if (b < 8) {
        int mat = b >> 2, h = b & 3;
        const float* w = (mat ? wtan : wrad) + h * F * F;
        __shared__ float sw[F * F];
        __shared__ float so[F * F];
        for (int i = tid; i < F * F; i += 256) {
            sw[i] = w[i];
            so[i] = wout[i];
        }
        __syncthreads();
        for (int idx = tid; idx < F * F; idx += 256) {
            int f = idx >> 6, go = idx & 63;
            float s = 0.0f;
#pragma unroll
            for (int g = 0; g < F; g++) s += sw[f * F + g] * so[g * F + go];
            g_M[((mat * 256) + h * 64 + f) * 64 + go] = 0.25f * s;
        }
    } else if (b == 8) {
        int h = tid >> 6;                    // tid = h*64 + f
        const float* wp = wprj + tid * F;
        float a = 0.0f, c = 0.0f;
#pragma unroll
        for (int g = 0; g < F; g++) {
            float w = wp[g];
            a += w * rscore[h * F + g];
            c += w * tscore[h * F + g];
        }
        g_vrad[tid] = a;
        g_vtan[tid] = c;
    } else {
        int i = (b - 9) * 256 + tid;
        if (i < n_nodes) g_cnt[i] = 0;
    }
}

// ------------------- K1b: node scalars (smem-staged) -------------------
#define SNB 32
__global__ void __launch_bounds__(256) k_scal(const float* __restrict__ x,
                                              int n_nodes) {
    __shared__ float xs[SNB][72];
    __shared__ float vs[8][68];
    int tid = threadIdx.x;
    int base = blockIdx.x * SNB;

    for (int i = tid; i < SNB * 16; i += 256) {
        int nl = i >> 4, fq = i & 15;
        int n = base + nl;
        float4 v = (n < n_nodes) ? *(const float4*)&x[n * F + fq * 4]
                                 : make_float4(0.f, 0.f, 0.f, 0.f);
        *(float4*)&xs[nl][fq * 4] = v;
    }
    if (tid < 128) {
        int row = tid >> 4, fq = tid & 15;
        int mat = row >> 2, h = row & 3;
        const float* src = (mat ? g_vtan : g_vrad) + h * F;
        *(float4*)&vs[row][fq * 4] = *(const float4*)&src[fq * 4];
    }
    __syncthreads();

    int nl = tid >> 3, c = tid & 7;
    int mat = c >> 2, h = c & 3;
    int n = base + nl;
    if (n >= n_nodes) return;
    const float* xr = xs[nl];
    const float* vv = vs[c];
    float s = 0.0f;
#pragma unroll
    for (int fq = 0; fq < 16; fq++) {
        float4 xv = *(const float4*)&xr[fq * 4];
        float4 v4 = *(const float4*)&vv[fq * 4];
        s += xv.x * v4.x + xv.y * v4.y + xv.z * v4.z + xv.w * v4.w;
    }
    if (mat) g_stan[n * H + h] = s;
    else     g_srad[n * H + h] = s;
}

// ------------------- K3: histogram by receiver (4 edges/thread) -------------------
__global__ void k_hist(const int* __restrict__ ei, int n_edges, int n_nodes) {
    int i = blockIdx.x * blockDim.x + threadIdx.x;
    int e0 = i * 4;
    if (e0 >= n_edges) return;
    if (((n_edges & 3) == 0) && (e0 + 3 < n_edges)) {
        int4 r4 = *(const int4*)&ei[n_edges + e0];
        if ((unsigned)r4.x < (unsigned)n_nodes) atomicAdd(&g_cnt[r4.x], 1);
        if ((unsigned)r4.y < (unsigned)n_nodes) atomicAdd(&g_cnt[r4.y], 1);
        if ((unsigned)r4.z < (unsigned)n_nodes) atomicAdd(&g_cnt[r4.z], 1);
        if ((unsigned)r4.w < (unsigned)n_nodes) atomicAdd(&g_cnt[r4.w], 1);
    } else {
        int e1 = min(e0 + 4, n_edges);
        for (int e = e0; e < e1; e++) {
            int r = ei[n_edges + e];
            if ((unsigned)r < (unsigned)n_nodes) atomicAdd(&g_cnt[r], 1);
        }
    }
}

// ------------------- K4a: scan stage 1 — per-block exclusive offsets + totals --
__global__ void __launch_bounds__(256) k_scan1(int n) {
    __shared__ int wsum[8];
    int b = blockIdx.x, t = threadIdx.x;
    int base = b * SCB + t * 4;

    int4 c = make_int4(0, 0, 0, 0);
    if (base + 3 < n) c = *(const int4*)&g_cnt[base];
    else {
        if (base + 0 < n) c.x = g_cnt[base + 0];
        if (base + 1 < n) c.y = g_cnt[base + 1];
        if (base + 2 < n) c.z = g_cnt[base + 2];
        if (base + 3 < n) c.w = g_cnt[base + 3];
    }
    int p0 = c.x, p1 = p0 + c.y, p2 = p1 + c.z, p3 = p2 + c.w;

    // warp inclusive scan of thread sums
    int lane = t & 31, wid = t >> 5;
    int incl = p3;
#pragma unroll
    for (int d = 1; d < 32; d <<= 1) {
        int v = __shfl_up_sync(0xffffffffu, incl, d);
        if (lane >= d) incl += v;
    }
    if (lane == 31) wsum[wid] = incl;
    __syncthreads();
    int wpre = 0;
    if (t < 8) {
        int v = wsum[t];
        int ws = v;
#pragma unroll
        for (int d = 1; d < 8; d <<= 1) {
            int u = __shfl_up_sync(0xffu, ws, d);
            if (t >= d) ws += u;
        }
        wsum[t] = ws - v;      // exclusive warp prefix
        if (t == 7) g_bsum[b] = ws;   // block total
    }
    __syncthreads();
    wpre = wsum[wid];
    int toff = wpre + incl - p3;      // exclusive offset of this thread

    // block-local exclusive per-element offsets
    int4 o;
    o.x = toff;
    o.y = toff + p0;
    o.z = toff + p1;
    o.w = toff + p2;
    if (base + 3 < n) *(int4*)&g_off[base] = o;
    else {
        if (base + 0 < n) g_off[base + 0] = o.x;
        if (base + 1 < n) g_off[base + 1] = o.y;
        if (base + 2 < n) g_off[base + 2] = o.z;
        if (base + 3 < n) g_off[base + 3] = o.w;
    }
}

// ------------------- K4b: scan stage 2 — add block prefix, write g_cur --------
__global__ void __launch_bounds__(256) k_scan2(int n, int nblocks) {
    int b = blockIdx.x, t = threadIdx.x;
    int pre = 0;
    for (int i = 0; i < b; i++) pre += g_bsum[i];

    int base = b * SCB + t * 4;
    if (base < n) {
        if (base + 3 < n) {
            int4 o = *(const int4*)&g_off[base];
            o.x += pre; o.y += pre; o.z += pre; o.w += pre;
            *(int4*)&g_off[base] = o;
            *(int4*)&g_cur[base] = o;
        } else {
            for (int j = 0; j < 4 && base + j < n; j++) {
                int v = g_off[base + j] + pre;
                g_off[base + j] = v;
                g_cur[base + j] = v;
            }
        }
    }
    if (b == 0 && t == 0) {
        int total = 0;
        for (int i = 0; i < nblocks; i++) total += g_bsum[i];
        g_off[n] = total;
    }
}

// ------------------- K5: scatter edges into CSR order (4 edges/thread) ---------
__global__ void k_sort(const int* __restrict__ ei,
                       const float* __restrict__ elen,
                       int n_edges, int n_nodes) {
    int i = blockIdx.x * blockDim.x + threadIdx.x;
    int e0 = i * 4;
    if (e0 >= n_edges) return;
    if (((n_edges & 3) == 0) && (e0 + 3 < n_edges)) {
        int4   s4 = *(const int4*)&ei[e0];
        int4   r4 = *(const int4*)&ei[n_edges + e0];
        float4 l4 = *(const float4*)&elen[e0];
        int   sa[4] = {s4.x, s4.y, s4.z, s4.w};
        int   ra[4] = {r4.x, r4.y, r4.z, r4.w};
        float la[4] = {l4.x, l4.y, l4.z, l4.w};
#pragma unroll
        for (int j = 0; j < 4; j++) {
            if ((unsigned)sa[j] >= (unsigned)n_nodes ||
                (unsigned)ra[j] >= (unsigned)n_nodes) continue;
            int pos = atomicAdd(&g_cur[ra[j]], 1);
            g_ss[pos] = sa[j];
            g_sl[pos] = la[j];
        }
    } else {
        int e1 = min(e0 + 4, n_edges);
        for (int e = e0; e < e1; e++) {
            int s = ei[e], r = ei[n_edges + e];
            if ((unsigned)s >= (unsigned)n_nodes ||
                (unsigned)r >= (unsigned)n_nodes) continue;
            int pos = atomicAdd(&g_cur[r], 1);
            g_ss[pos] = s;
            g_sl[pos] = elen[e];
        }
    }
}

// ------------------- K6: per-receiver softmax + weighted-x aggregation ---------
__global__ void __launch_bounds__(256) k_main(const float* __restrict__ xp,
                                              const float* __restrict__ rdls,
                                              const float* __restrict__ rtb,
                                              const float* __restrict__ rtw,
                                              const float* __restrict__ mixb,
                                              const float* __restrict__ mixs,
                                              int n_nodes) {
    int r = (blockIdx.x * blockDim.x + threadIdx.x) >> 5;
    int lane = threadIdx.x & 31;
    if (r >= n_nodes) return;
    int beg = g_off[r], end = g_off[r + 1];

    float2* Ar = (float2*)&g_A[r * 512];

    if (beg == end) {
        float2 z = make_float2(0.0f, 0.0f);
#pragma unroll
        for (int c = 0; c < 8; c++) Ar[c * 32 + lane] = z;
        return;
    }

    float dist_scale = softplus_f(rdls[0]);
    float4 tb = *(const float4*)rtb;
    float4 tw = *(const float4*)rtw;
    float4 mb = *(const float4*)mixb;
    float4 ms = *(const float4*)mixs;
    float4 srr = *(const float4*)&g_srad[r * 4];
    float4 str = *(const float4*)&g_stan[r * 4];

    const float NEG = __int_as_float(0xff800000);
    float mr0 = NEG, mr1 = NEG, mr2 = NEG, mr3 = NEG;
    float mt0 = NEG, mt1 = NEG, mt2 = NEG, mt3 = NEG;

    // ---- pass A: compute + STORE logits, take per-head max ----
    for (int i = beg + lane; i < end; i += 32) {
        int s = g_ss[i];
        float len = g_sl[i];
        float4 ss = *(const float4*)&g_srad[s * 4];
        float4 ts = *(const float4*)&g_stan[s * 4];
        float c = dist_scale * len;
        float t0 = softplus_f(tb.x + tw.x * len) + 1e-4f;
        float t1 = softplus_f(tb.y + tw.y * len) + 1e-4f;
        float t2 = softplus_f(tb.z + tw.z * len) + 1e-4f;
        float t3 = softplus_f(tb.w + tw.w * len) + 1e-4f;
        float4 rl, tl;
        rl.x = (ss.x - srr.x - c) / t0;
        rl.y = (ss.y - srr.y - c) / t1;
        rl.z = (ss.z - srr.z - c) / t2;
        rl.w = (ss.w - srr.w - c) / t3;
        tl.x = ts.x - str.x;
        tl.y = ts.y - str.y;
        tl.z = ts.z - str.z;
        tl.w = ts.w - str.w;
        g_er[i] = rl;
        g_et[i] = tl;
        mr0 = fmaxf(mr0, rl.x); mr1 = fmaxf(mr1, rl.y);
        mr2 = fmaxf(mr2, rl.z); mr3 = fmaxf(mr3, rl.w);
        mt0 = fmaxf(mt0, tl.x); mt1 = fmaxf(mt1, tl.y);
        mt2 = fmaxf(mt2, tl.z); mt3 = fmaxf(mt3, tl.w);
    }
    mr0 = wred_max(mr0); mr1 = wred_max(mr1); mr2 = wred_max(mr2); mr3 = wred_max(mr3);
    mt0 = wred_max(mt0); mt1 = wred_max(mt1); mt2 = wred_max(mt2); mt3 = wred_max(mt3);

    // ---- pass B: exps (from stored logits) + denominators ----
    float dr0 = 0, dr1 = 0, dr2 = 0, dr3 = 0;
    float dt0 = 0, dt1 = 0, dt2 = 0, dt3 = 0;
    for (int i = beg + lane; i < end; i += 32) {
        float4 rl = g_er[i];
        float4 tl = g_et[i];
        float4 er, et;
        er.x = __expf(rl.x - mr0);
        er.y = __expf(rl.y - mr1);
        er.z = __expf(rl.z - mr2);
        er.w = __expf(rl.w - mr3);
        et.x = __expf(tl.x - mt0);
        et.y = __expf(tl.y - mt1);
        et.z = __expf(tl.z - mt2);
        et.w = __expf(tl.w - mt3);
        g_er[i] = er;
        g_et[i] = et;
        dr0 += er.x; dr1 += er.y; dr2 += er.z; dr3 += er.w;
        dt0 += et.x; dt1 += et.y; dt2 += et.z; dt3 += et.w;
    }
    dr0 = wred_sum(dr0); dr1 = wred_sum(dr1); dr2 = wred_sum(dr2); dr3 = wred_sum(dr3);
    dt0 = wred_sum(dt0); dt1 = wred_sum(dt1); dt2 = wred_sum(dt2); dt3 = wred_sum(dt3);
    dr0 = 1.0f / (dr0 + 1e-9f); dr1 = 1.0f / (dr1 + 1e-9f);
    dr2 = 1.0f / (dr2 + 1e-9f); dr3 = 1.0f / (dr3 + 1e-9f);
    dt0 = 1.0f / (dt0 + 1e-9f); dt1 = 1.0f / (dt1 + 1e-9f);
    dt2 = 1.0f / (dt2 + 1e-9f); dt3 = 1.0f / (dt3 + 1e-9f);

    // ---- pass B2: per-edge blended weights + receiver-side totals ----
    float W10 = 0, W11 = 0, W12 = 0, W13 = 0;
    float W20 = 0, W21 = 0, W22 = 0, W23 = 0;
    for (int i = beg + lane; i < end; i += 32) {
        float len = g_sl[i];
        float4 er = g_er[i];
        float4 et = g_et[i];
        float g0 = sigmoid_f(mb.x + ms.x * len);
        float g1 = sigmoid_f(mb.y + ms.y * len);
        float g2 = sigmoid_f(mb.z + ms.z * len);
        float g3 = sigmoid_f(mb.w + ms.w * len);
        float b0 = g0 * er.x * dr0 + (1.0f - g0) * et.x * dt0;
        float b1 = g1 * er.y * dr1 + (1.0f - g1) * et.y * dt1;
        float b2 = g2 * er.z * dr2 + (1.0f - g2) * et.z * dt2;
        float b3 = g3 * er.w * dr3 + (1.0f - g3) * et.w * dt3;
        float4 w1, w2;
        w1.x = b0 * g0; w2.x = b0 * (1.0f - g0);
        w1.y = b1 * g1; w2.y = b1 * (1.0f - g1);
        w1.z = b2 * g2; w2.z = b2 * (1.0f - g2);
        w1.w = b3 * g3; w2.w = b3 * (1.0f - g3);
        g_w1[i] = w1;
        g_w2[i] = w2;
        W10 += w1.x; W11 += w1.y; W12 += w1.z; W13 += w1.w;
        W20 += w2.x; W21 += w2.y; W22 += w2.z; W23 += w2.w;
    }
    W10 = wred_sum(W10); W11 = wred_sum(W11); W12 = wred_sum(W12); W13 = wred_sum(W13);
    W20 = wred_sum(W20); W21 = wred_sum(W21); W22 = wred_sum(W22); W23 = wred_sum(W23);

    // ---- pass C: gather raw x[s], accumulate 8 weighted sums (pipelined) ----
    const float2* Xp = (const float2*)xp;
    float2 a10 = {0,0}, a11 = {0,0}, a12 = {0,0}, a13 = {0,0};
    float2 a20 = {0,0}, a21 = {0,0}, a22 = {0,0}, a23 = {0,0};
    int    s_cur = g_ss[beg];
    float4 w1c   = g_w1[beg];
    float4 w2c   = g_w2[beg];
    for (int i = beg; i < end; i++) {
        float2 xv = Xp[s_cur * 32 + lane];
        if (i + 1 < end) s_cur = g_ss[i + 1];
        float4 w1 = w1c, w2 = w2c;
        if (i + 1 < end) { w1c = g_w1[i + 1]; w2c = g_w2[i + 1]; }
        a10.x += w1.x * xv.x; a10.y += w1.x * xv.y;
        a11.x += w1.y * xv.x; a11.y += w1.y * xv.y;
        a12.x += w1.z * xv.x; a12.y += w1.z * xv.y;
        a13.x += w1.w * xv.x; a13.y += w1.w * xv.y;
        a20.x += w2.x * xv.x; a20.y += w2.x * xv.y;
        a21.x += w2.y * xv.x; a21.y += w2.y * xv.y;
        a22.x += w2.z * xv.x; a22.y += w2.z * xv.y;
        a23.x += w2.w * xv.x; a23.y += w2.w * xv.y;
    }
    {
        float2 xr = Xp[r * 32 + lane];
        a10.x -= W10 * xr.x; a10.y -= W10 * xr.y;
        a11.x -= W11 * xr.x; a11.y -= W11 * xr.y;
        a12.x -= W12 * xr.x; a12.y -= W12 * xr.y;
        a13.x -= W13 * xr.x; a13.y -= W13 * xr.y;
        a20.x -= W20 * xr.x; a20.y -= W20 * xr.y;
        a21.x -= W21 * xr.x; a21.y -= W21 * xr.y;
        a22.x -= W22 * xr.x; a22.y -= W22 * xr.y;
        a23.x -= W23 * xr.x; a23.y -= W23 * xr.y;
    }
    Ar[0 * 32 + lane] = a10;
    Ar[1 * 32 + lane] = a11;
    Ar[2 * 32 + lane] = a12;
    Ar[3 * 32 + lane] = a13;
    Ar[4 * 32 + lane] = a20;
    Ar[5 * 32 + lane] = a21;
    Ar[6 * 32 + lane] = a22;
    Ar[7 * 32 + lane] = a23;
}

// ------------------- K7: out = x + A @ M  (fused proj + head-mean + w_out) ----
#define PNB 64
__global__ void __launch_bounds__(256) k_post(const float* __restrict__ x,
                                              float* __restrict__ out,
                                              int n_nodes) {
    int tid = threadIdx.x;
    int ng  = tid >> 4;
    int goq = tid & 15;
    int n0 = blockIdx.x * PNB + ng * 4;

    const float4* Mp = (const float4*)g_M;
    float4 acc0 = {0,0,0,0}, acc1 = {0,0,0,0}, acc2 = {0,0,0,0}, acc3 = {0,0,0,0};

    const float* A0 = &g_A[(size_t)n0 * 512];

#pragma unroll 2
    for (int k = 0; k < 512; k += 4) {
        float4 m0 = __ldg(&Mp[(k + 0) * 16 + goq]);
        float4 m1 = __ldg(&Mp[(k + 1) * 16 + goq]);
        float4 m2 = __ldg(&Mp[(k + 2) * 16 + goq]);
        float4 m3 = __ldg(&Mp[(k + 3) * 16 + goq]);
        float4 a0 = *(const float4*)&A0[0 * 512 + k];
        float4 a1 = *(const float4*)&A0[1 * 512 + k];
        float4 a2 = *(const float4*)&A0[2 * 512 + k];
        float4 a3 = *(const float4*)&A0[3 * 512 + k];
        acc0.x += a0.x * m0.x + a0.y * m1.x + a0.z * m2.x + a0.w * m3.x;
        acc0.y += a0.x * m0.y + a0.y * m1.y + a0.z * m2.y + a0.w * m3.y;
        acc0.z += a0.x * m0.z + a0.y * m1.z + a0.z * m2.z + a0.w * m3.z;
        acc0.w += a0.x * m0.w + a0.y * m1.w + a0.z * m2.w + a0.w * m3.w;
        acc1.x += a1.x * m0.x + a1.y * m1.x + a1.z * m2.x + a1.w * m3.x;
        acc1.y += a1.x * m0.y + a1.y * m1.y + a1.z * m2.y + a1.w * m3.y;
        acc1.z += a1.x * m0.z + a1.y * m1.z + a1.z * m2.z + a1.w * m3.z;
        acc1.w += a1.x * m0.w + a1.y * m1.w + a1.z * m2.w + a1.w * m3.w;
        acc2.x += a2.x * m0.x + a2.y * m1.x + a2.z * m2.x + a2.w * m3.x;
        acc2.y += a2.x * m0.y + a2.y * m1.y + a2.z * m2.y + a2.w * m3.y;
        acc2.z += a2.x * m0.z + a2.y * m1.z + a2.z * m2.z + a2.w * m3.z;
        acc2.w += a2.x * m0.w + a2.y * m1.w + a2.z * m2.w + a2.w * m3.w;
        acc3.x += a3.x * m0.x + a3.y * m1.x + a3.z * m2.x + a3.w * m3.x;
        acc3.y += a3.x * m0.y + a3.y * m1.y + a3.z * m2.y + a3.w * m3.y;
        acc3.z += a3.x * m0.z + a3.y * m1.z + a3.z * m2.z + a3.w * m3.z;
        acc3.w += a3.x * m0.w + a3.y * m1.w + a3.z * m2.w + a3.w * m3.w;
    }

    float4 accs[4] = {acc0, acc1, acc2, acc3};
#pragma unroll
    for (int j = 0; j < 4; j++) {
        int n = n0 + j;
        if (n >= n_nodes) break;
        float4 xv = *(const float4*)&x[n * F + goq * 4];
        float4 o;
        o.x = xv.x + accs[j].x;
        o.y = xv.y + accs[j].y;
        o.z = xv.z + accs[j].z;
        o.w = xv.w + accs[j].w;
        *(float4*)&out[n * F + goq * 4] = o;
    }
}

// ------------------- launch -------------------
extern "C" void kernel_launch(void* const* d_in, const int* in_sizes, int n_in,
                              void* d_out, int out_size) {
    const float* x     = (const float*)d_in[0];
    const int*   ei    = (const int*)d_in[1];     // edge_index staged as int32, [2, E]
    // d_in[2] = edge_vec (unused by reference)
    const float* elen  = (const float*)d_in[3];
    const float* wprj  = (const float*)d_in[4];
    const float* wrad  = (const float*)d_in[5];
    const float* wtan  = (const float*)d_in[6];
    const float* rsc   = (const float*)d_in[7];
    const float* tsc   = (const float*)d_in[8];
    const float* rdls  = (const float*)d_in[9];
    const float* rtb   = (const float*)d_in[10];
    const float* rtw   = (const float*)d_in[11];
    const float* mixb  = (const float*)d_in[12];
    const float* mixs  = (const float*)d_in[13];
    const float* wout  = (const float*)d_in[14];
    float*       out   = (float*)d_out;

    int n_nodes = in_sizes[0] / F;
    int n_edges = in_sizes[3];

    k_setup<<<9 + (n_nodes + 255) / 256, 256>>>(wrad, wtan, wout,
                                                wprj, rsc, tsc, n_nodes);
    k_scal<<<(n_nodes + SNB - 1) / SNB, 256>>>(x, n_nodes);

    int ethreads = (n_edges + 3) / 4;
    k_hist<<<(ethreads + 255) / 256, 256>>>(ei, n_edges, n_nodes);

    int sblocks = (n_nodes + SCB - 1) / SCB;
    k_scan1<<<sblocks, 256>>>(n_nodes);
    k_scan2<<<sblocks, 256>>>(n_nodes, sblocks);

    k_sort<<<(ethreads + 255) / 256, 256>>>(ei, elen, n_edges, n_nodes);

    k_main<<<(n_nodes * 32 + 255) / 256, 256>>>(x, rdls, rtb, rtw, mixb, mixs, n_nodes);
    k_post<<<(n_nodes + PNB - 1) / PNB, 256>>>(x, out, n_nodes);
}

// round 16
// speedup vs baseline: 1.4412x; 1.0004x over previous
#include <cuda_runtime.h>
#include <cuda_bf16.h>
#include <cuda_fp16.h>
#include <cstdint>

#define NMAX 20000
#define NPAD 20032          // padded to 64-node blocks for k_post
#define EMAX 320000
#define F 64
#define H 4
#define SCB 1024            // elements per scan block

// ------------------- scratch (static device globals; no allocation) -------------------
__device__ float   g_srad[NMAX * H];      // [n][h]
__device__ float   g_stan[NMAX * H];
__device__ float   g_vrad[H * F];         // w_proj @ radial_score
__device__ float   g_vtan[H * F];
__device__ float   g_A[NPAD * 512];       // per-receiver weighted-x sums [n][mat*256+h*64+f]
__device__ float   g_M[512 * 64];         // combined (1/4)·w_{mat,h} @ w_out

// CSR sort scratch
__device__ int     g_cnt[NMAX];
__device__ int     g_off[NMAX + 1];
__device__ int     g_cur[NMAX];
__device__ int     g_bsum[64];            // per-scan-block totals
__device__ int     g_ss[EMAX];            // sorted sender
__device__ float   g_sl[EMAX];            // sorted edge_len
__device__ float4  g_er[EMAX];            // pass A: radial logits; pass B: exps
__device__ float4  g_et[EMAX];            // pass A: tangential logits; pass B: exps
__device__ float4  g_w1[EMAX];            // per-edge blended weights (radial side)
__device__ float4  g_w2[EMAX];            // per-edge blended weights (tangential side)

// ------------------- helpers -------------------
__device__ __forceinline__ float softplus_f(float v) {
    return (v > 20.0f) ? v : log1pf(__expf(v));
}
__device__ __forceinline__ float sigmoid_f(float v) {
    return 1.0f / (1.0f + __expf(-v));
}
__device__ __forceinline__ float wred_max(float v) {
#pragma unroll
    for (int d = 16; d; d >>= 1) v = fmaxf(v, __shfl_xor_sync(0xffffffffu, v, d));
    return v;
}
__device__ __forceinline__ float wred_sum(float v) {
#pragma unroll
    for (int d = 16; d; d >>= 1) v += __shfl_xor_sync(0xffffffffu, v, d);
    return v;
}

// ------------------- K0: fused setup (prep-M | score vectors | zero counters) --
__global__ void k_setup(const float* __restrict__ wrad,
                        const float* __restrict__ wtan,
                        const float* __restrict__ wout,
                        const float* __restrict__ wprj,
                        const float* __restrict__ rscore,
                        const float* __restrict__ tscore,
                        int n_nodes) {
    int b = blockIdx.x;
    int tid = threadIdx.x;
    if (b < 8) {
        int mat = b >> 2, h = b & 3;
        const float* w = (mat ? wtan : wrad) + h * F * F;
        __shared__ float sw[F * F];
        __shared__ float so[F * F];
        for (int i = tid; i < F * F; i += 256) {
            sw[i] = w[i];
            so[i] = wout[i];
        }
        __syncthreads();
        for (int idx = tid; idx < F * F; idx += 256) {
            int f = idx >> 6, go = idx & 63;
            float s = 0.0f;
#pragma unroll
            for (int g = 0; g < F; g++) s += sw[f * F + g] * so[g * F + go];
            g_M[((mat * 256) + h * 64 + f) * 64 + go] = 0.25f * s;
        }
    } else if (b == 8) {
        int h = tid >> 6;                    // tid = h*64 + f
        const float* wp = wprj + tid * F;
        float a = 0.0f, c = 0.0f;
#pragma unroll
        for (int g = 0; g < F; g++) {
            float w = wp[g];
            a += w * rscore[h * F + g];
            c += w * tscore[h * F + g];
        }
        g_vrad[tid] = a;
        g_vtan[tid] = c;
    } else {
        int i = (b - 9) * 256 + tid;
        if (i < n_nodes) g_cnt[i] = 0;
    }
}

// ------------------- K1b: node scalars (smem-staged) -------------------
#define SNB 32
__global__ void __launch_bounds__(256) k_scal(const float* __restrict__ x,
                                              int n_nodes) {
    __shared__ float xs[SNB][72];
    __shared__ float vs[8][68];
    int tid = threadIdx.x;
    int base = blockIdx.x * SNB;

    for (int i = tid; i < SNB * 16; i += 256) {
        int nl = i >> 4, fq = i & 15;
        int n = base + nl;
        float4 v = (n < n_nodes) ? *(const float4*)&x[n * F + fq * 4]
                                 : make_float4(0.f, 0.f, 0.f, 0.f);
        *(float4*)&xs[nl][fq * 4] = v;
    }
    if (tid < 128) {
        int row = tid >> 4, fq = tid & 15;
        int mat = row >> 2, h = row & 3;
        const float* src = (mat ? g_vtan : g_vrad) + h * F;
        *(float4*)&vs[row][fq * 4] = *(const float4*)&src[fq * 4];
    }
    __syncthreads();

    int nl = tid >> 3, c = tid & 7;
    int mat = c >> 2, h = c & 3;
    int n = base + nl;
    if (n >= n_nodes) return;
    const float* xr = xs[nl];
    const float* vv = vs[c];
    float s = 0.0f;
#pragma unroll
    for (int fq = 0; fq < 16; fq++) {
        float4 xv = *(const float4*)&xr[fq * 4];
        float4 v4 = *(const float4*)&vv[fq * 4];
        s += xv.x * v4.x + xv.y * v4.y + xv.z * v4.z + xv.w * v4.w;
    }
    if (mat) g_stan[n * H + h] = s;
    else     g_srad[n * H + h] = s;
}

// ------------------- K3: histogram by receiver (4 edges/thread) -------------------
__global__ void k_hist(const int* __restrict__ ei, int n_edges, int n_nodes) {
    int i = blockIdx.x * blockDim.x + threadIdx.x;
    int e0 = i * 4;
    if (e0 >= n_edges) return;
    if (((n_edges & 3) == 0) && (e0 + 3 < n_edges)) {
        int4 r4 = *(const int4*)&ei[n_edges + e0];
        if ((unsigned)r4.x < (unsigned)n_nodes) atomicAdd(&g_cnt[r4.x], 1);
        if ((unsigned)r4.y < (unsigned)n_nodes) atomicAdd(&g_cnt[r4.y], 1);
        if ((unsigned)r4.z < (unsigned)n_nodes) atomicAdd(&g_cnt[r4.z], 1);
        if ((unsigned)r4.w < (unsigned)n_nodes) atomicAdd(&g_cnt[r4.w], 1);
    } else {
        int e1 = min(e0 + 4, n_edges);
        for (int e = e0; e < e1; e++) {
            int r = ei[n_edges + e];
            if ((unsigned)r < (unsigned)n_nodes) atomicAdd(&g_cnt[r], 1);
        }
    }
}

// ------------------- K4a: scan stage 1 — per-block exclusive offsets + totals --
__global__ void __launch_bounds__(256) k_scan1(int n) {
    __shared__ int wsum[8];
    int b = blockIdx.x, t = threadIdx.x;
    int base = b * SCB + t * 4;

    int4 c = make_int4(0, 0, 0, 0);
    if (base + 3 < n) c = *(const int4*)&g_cnt[base];
    else {
        if (base + 0 < n) c.x = g_cnt[base + 0];
        if (base + 1 < n) c.y = g_cnt[base + 1];
        if (base + 2 < n) c.z = g_cnt[base + 2];
        if (base + 3 < n) c.w = g_cnt[base + 3];
    }
    int p0 = c.x, p1 = p0 + c.y, p2 = p1 + c.z, p3 = p2 + c.w;

    int lane = t & 31, wid = t >> 5;
    int incl = p3;
#pragma unroll
    for (int d = 1; d < 32; d <<= 1) {
        int v = __shfl_up_sync(0xffffffffu, incl, d);
        if (lane >= d) incl += v;
    }
    if (lane == 31) wsum[wid] = incl;
    __syncthreads();
    int wpre = 0;
    if (t < 8) {
        int v = wsum[t];
        int ws = v;
#pragma unroll
        for (int d = 1; d < 8; d <<= 1) {
            int u = __shfl_up_sync(0xffu, ws, d);
            if (t >= d) ws += u;
        }
        wsum[t] = ws - v;      // exclusive warp prefix
        if (t == 7) g_bsum[b] = ws;   // block total
    }
    __syncthreads();
    wpre = wsum[wid];
    int toff = wpre + incl - p3;

    int4 o;
    o.x = toff;
    o.y = toff + p0;
    o.z = toff + p1;
    o.w = toff + p2;
    if (base + 3 < n) *(int4*)&g_off[base] = o;
    else {
        if (base + 0 < n) g_off[base + 0] = o.x;
        if (base + 1 < n) g_off[base + 1] = o.y;
        if (base + 2 < n) g_off[base + 2] = o.z;
        if (base + 3 < n) g_off[base + 3] = o.w;
    }
}

// ------------------- K4b: scan stage 2 — add block prefix, write g_cur --------
__global__ void __launch_bounds__(256) k_scan2(int n, int nblocks) {
    int b = blockIdx.x, t = threadIdx.x;
    int pre = 0;
    for (int i = 0; i < b; i++) pre += g_bsum[i];

    int base = b * SCB + t * 4;
    if (base < n) {
        if (base + 3 < n) {
            int4 o = *(const int4*)&g_off[base];
            o.x += pre; o.y += pre; o.z += pre; o.w += pre;
            *(int4*)&g_off[base] = o;
            *(int4*)&g_cur[base] = o;
        } else {
            for (int j = 0; j < 4 && base + j < n; j++) {
                int v = g_off[base + j] + pre;
                g_off[base + j] = v;
                g_cur[base + j] = v;
            }
        }
    }
    if (b == 0 && t == 0) {
        int total = 0;
        for (int i = 0; i < nblocks; i++) total += g_bsum[i];
        g_off[n] = total;
    }
}

// ------------------- K5: scatter edges into CSR order (4 edges/thread) ---------
__global__ void k_sort(const int* __restrict__ ei,
                       const float* __restrict__ elen,
                       int n_edges, int n_nodes) {
    int i = blockIdx.x * blockDim.x + threadIdx.x;
    int e0 = i * 4;
    if (e0 >= n_edges) return;
    if (((n_edges & 3) == 0) && (e0 + 3 < n_edges)) {
        int4   s4 = *(const int4*)&ei[e0];
        int4   r4 = *(const int4*)&ei[n_edges + e0];
        float4 l4 = *(const float4*)&elen[e0];
        int   sa[4] = {s4.x, s4.y, s4.z, s4.w};
        int   ra[4] = {r4.x, r4.y, r4.z, r4.w};
        float la[4] = {l4.x, l4.y, l4.z, l4.w};
#pragma unroll
        for (int j = 0; j < 4; j++) {
            if ((unsigned)sa[j] >= (unsigned)n_nodes ||
                (unsigned)ra[j] >= (unsigned)n_nodes) continue;
            int pos = atomicAdd(&g_cur[ra[j]], 1);
            g_ss[pos] = sa[j];
            g_sl[pos] = la[j];
        }
    } else {
        int e1 = min(e0 + 4, n_edges);
        for (int e = e0; e < e1; e++) {
            int s = ei[e], r = ei[n_edges + e];
            if ((unsigned)s >= (unsigned)n_nodes ||
                (unsigned)r >= (unsigned)n_nodes) continue;
            int pos = atomicAdd(&g_cur[r], 1);
            g_ss[pos] = s;
            g_sl[pos] = elen[e];
        }
    }
}

// ------------------- K6: per-receiver softmax + weighted-x aggregation ---------
// warp per receiver; pass C: TWO edges in flight (half-warp each, 16 lanes x float4).
__global__ void __launch_bounds__(256) k_main(const float* __restrict__ xp,
                                              const float* __restrict__ rdls,
                                              const float* __restrict__ rtb,
                                              const float* __restrict__ rtw,
                                              const float* __restrict__ mixb,
                                              const float* __restrict__ mixs,
                                              int n_nodes) {
    int r = (blockIdx.x * blockDim.x + threadIdx.x) >> 5;
    int lane = threadIdx.x & 31;
    if (r >= n_nodes) return;
    int beg = g_off[r], end = g_off[r + 1];

    float4* Ar4 = (float4*)&g_A[r * 512];   // channel c at c*16 + (f/4)

    if (beg == end) {
        float4 z = make_float4(0.f, 0.f, 0.f, 0.f);
        int hl = lane & 15;
        int c0 = (lane >> 4) * 4;
#pragma unroll
        for (int c = 0; c < 4; c++) Ar4[(c0 + c) * 16 + hl] = z;
        return;
    }

    float dist_scale = softplus_f(rdls[0]);
    float4 tb = *(const float4*)rtb;
    float4 tw = *(const float4*)rtw;
    float4 mb = *(const float4*)mixb;
    float4 ms = *(const float4*)mixs;
    float4 srr = *(const float4*)&g_srad[r * 4];
    float4 str = *(const float4*)&g_stan[r * 4];

    const float NEG = __int_as_float(0xff800000);
    float mr0 = NEG, mr1 = NEG, mr2 = NEG, mr3 = NEG;
    float mt0 = NEG, mt1 = NEG, mt2 = NEG, mt3 = NEG;

    // ---- pass A: compute + STORE logits, take per-head max ----
    for (int i = beg + lane; i < end; i += 32) {
        int s = g_ss[i];
        float len = g_sl[i];
        float4 ss = *(const float4*)&g_srad[s * 4];
        float4 ts = *(const float4*)&g_stan[s * 4];
        float c = dist_scale * len;
        float t0 = softplus_f(tb.x + tw.x * len) + 1e-4f;
        float t1 = softplus_f(tb.y + tw.y * len) + 1e-4f;
        float t2 = softplus_f(tb.z + tw.z * len) + 1e-4f;
        float t3 = softplus_f(tb.w + tw.w * len) + 1e-4f;
        float4 rl, tl;
        rl.x = (ss.x - srr.x - c) / t0;
        rl.y = (ss.y - srr.y - c) / t1;
        rl.z = (ss.z - srr.z - c) / t2;
        rl.w = (ss.w - srr.w - c) / t3;
        tl.x = ts.x - str.x;
        tl.y = ts.y - str.y;
        tl.z = ts.z - str.z;
        tl.w = ts.w - str.w;
        g_er[i] = rl;
        g_et[i] = tl;
        mr0 = fmaxf(mr0, rl.x); mr1 = fmaxf(mr1, rl.y);
        mr2 = fmaxf(mr2, rl.z); mr3 = fmaxf(mr3, rl.w);
        mt0 = fmaxf(mt0, tl.x); mt1 = fmaxf(mt1, tl.y);
        mt2 = fmaxf(mt2, tl.z); mt3 = fmaxf(mt3, tl.w);
    }
    mr0 = wred_max(mr0); mr1 = wred_max(mr1); mr2 = wred_max(mr2); mr3 = wred_max(mr3);
    mt0 = wred_max(mt0); mt1 = wred_max(mt1); mt2 = wred_max(mt2); mt3 = wred_max(mt3);

    // ---- pass B: exps (from stored logits) + denominators ----
    float dr0 = 0, dr1 = 0, dr2 = 0, dr3 = 0;
    float dt0 = 0, dt1 = 0, dt2 = 0, dt3 = 0;
    for (int i = beg + lane; i < end; i += 32) {
        float4 rl = g_er[i];
        float4 tl = g_et[i];
        float4 er, et;
        er.x = __expf(rl.x - mr0);
        er.y = __expf(rl.y - mr1);
        er.z = __expf(rl.z - mr2);
        er.w = __expf(rl.w - mr3);
        et.x = __expf(tl.x - mt0);
        et.y = __expf(tl.y - mt1);
        et.z = __expf(tl.z - mt2);
        et.w = __expf(tl.w - mt3);
        g_er[i] = er;
        g_et[i] = et;
        dr0 += er.x; dr1 += er.y; dr2 += er.z; dr3 += er.w;
        dt0 += et.x; dt1 += et.y; dt2 += et.z; dt3 += et.w;
    }
    dr0 = wred_sum(dr0); dr1 = wred_sum(dr1); dr2 = wred_sum(dr2); dr3 = wred_sum(dr3);
    dt0 = wred_sum(dt0); dt1 = wred_sum(dt1); dt2 = wred_sum(dt2); dt3 = wred_sum(dt3);
    dr0 = 1.0f / (dr0 + 1e-9f); dr1 = 1.0f / (dr1 + 1e-9f);
    dr2 = 1.0f / (dr2 + 1e-9f); dr3 = 1.0f / (dr3 + 1e-9f);
    dt0 = 1.0f / (dt0 + 1e-9f); dt1 = 1.0f / (dt1 + 1e-9f);
    dt2 = 1.0f / (dt2 + 1e-9f); dt3 = 1.0f / (dt3 + 1e-9f);

    // ---- pass B2: per-edge blended weights + receiver-side totals ----
    float W10 = 0, W11 = 0, W12 = 0, W13 = 0;
    float W20 = 0, W21 = 0, W22 = 0, W23 = 0;
    for (int i = beg + lane; i < end; i += 32) {
        float len = g_sl[i];
        float4 er = g_er[i];
        float4 et = g_et[i];
        float g0 = sigmoid_f(mb.x + ms.x * len);
        float g1 = sigmoid_f(mb.y + ms.y * len);
        float g2 = sigmoid_f(mb.z + ms.z * len);
        float g3 = sigmoid_f(mb.w + ms.w * len);
        float b0 = g0 * er.x * dr0 + (1.0f - g0) * et.x * dt0;
        float b1 = g1 * er.y * dr1 + (1.0f - g1) * et.y * dt1;
        float b2 = g2 * er.z * dr2 + (1.0f - g2) * et.z * dt2;
        float b3 = g3 * er.w * dr3 + (1.0f - g3) * et.w * dt3;
        float4 w1, w2;
        w1.x = b0 * g0; w2.x = b0 * (1.0f - g0);
        w1.y = b1 * g1; w2.y = b1 * (1.0f - g1);
        w1.z = b2 * g2; w2.z = b2 * (1.0f - g2);
        w1.w = b3 * g3; w2.w = b3 * (1.0f - g3);
        g_w1[i] = w1;
        g_w2[i] = w2;
        W10 += w1.x; W11 += w1.y; W12 += w1.z; W13 += w1.w;
        W20 += w2.x; W21 += w2.y; W22 += w2.z; W23 += w2.w;
    }
    W10 = wred_sum(W10); W11 = wred_sum(W11); W12 = wred_sum(W12); W13 = wred_sum(W13);
    W20 = wred_sum(W20); W21 = wred_sum(W21); W22 = wred_sum(W22); W23 = wred_sum(W23);

    // ---- pass C: two edges in flight — half-warp per edge, 16 lanes x float4 ----
    const float4* Xp4 = (const float4*)xp;   // 16 float4 per node
    int half = lane >> 4;        // 0 or 1: which edge stream
    int hl   = lane & 15;        // feature quad within node
    float4 A0 = {0,0,0,0}, A1 = {0,0,0,0}, A2 = {0,0,0,0}, A3 = {0,0,0,0};
    float4 A4 = {0,0,0,0}, A5 = {0,0,0,0}, A6 = {0,0,0,0}, A7 = {0,0,0,0};

    int i0 = beg + half;
    if (i0 < end) {
        int    s_cur = g_ss[i0];
        float4 w1c   = g_w1[i0];
        float4 w2c   = g_w2[i0];
        for (int i = i0; i < end; i += 2) {
            float4 xv = Xp4[s_cur * 16 + hl];
            float4 w1 = w1c, w2 = w2c;
            if (i + 2 < end) {
                s_cur = g_ss[i + 2];
                w1c = g_w1[i + 2];
                w2c = g_w2[i + 2];
            }
            A0.x += w1.x * xv.x; A0.y += w1.x * xv.y; A0.z += w1.x * xv.z; A0.w += w1.x * xv.w;
            A1.x += w1.y * xv.x; A1.y += w1.y * xv.y; A1.z += w1.y * xv.z; A1.w += w1.y * xv.w;
            A2.x += w1.z * xv.x; A2.y += w1.z * xv.y; A2.z += w1.z * xv.z; A2.w += w1.z * xv.w;
            A3.x += w1.w * xv.x; A3.y += w1.w * xv.y; A3.z += w1.w * xv.z; A3.w += w1.w * xv.w;
            A4.x += w2.x * xv.x; A4.y += w2.x * xv.y; A4.z += w2.x * xv.z; A4.w += w2.x * xv.w;
            A5.x += w2.y * xv.x; A5.y += w2.y * xv.y; A5.z += w2.y * xv.z; A5.w += w2.y * xv.w;
            A6.x += w2.z * xv.x; A6.y += w2.z * xv.y; A6.z += w2.z * xv.z; A6.w += w2.z * xv.w;
            A7.x += w2.w * xv.x; A7.y += w2.w * xv.y; A7.z += w2.w * xv.z; A7.w += w2.w * xv.w;
        }
    }

    // merge half-warps (xor-16 add, both halves end with full sums)
#define MERGE(A) \
    A.x += __shfl_xor_sync(0xffffffffu, A.x, 16); \
    A.y += __shfl_xor_sync(0xffffffffu, A.y, 16); \
    A.z += __shfl_xor_sync(0xffffffffu, A.z, 16); \
    A.w += __shfl_xor_sync(0xffffffffu, A.w, 16);
    MERGE(A0) MERGE(A1) MERGE(A2) MERGE(A3)
    MERGE(A4) MERGE(A5) MERGE(A6) MERGE(A7)
#undef MERGE

    // receiver correction (both halves compute identically)
    {
        float4 xr = Xp4[r * 16 + hl];
        A0.x -= W10 * xr.x; A0.y -= W10 * xr.y; A0.z -= W10 * xr.z; A0.w -= W10 * xr.w;
        A1.x -= W11 * xr.x; A1.y -= W11 * xr.y; A1.z -= W11 * xr.z; A1.w -= W11 * xr.w;
        A2.x -= W12 * xr.x; A2.y -= W12 * xr.y; A2.z -= W12 * xr.z; A2.w -= W12 * xr.w;
        A3.x -= W13 * xr.x; A3.y -= W13 * xr.y; A3.z -= W13 * xr.z; A3.w -= W13 * xr.w;
        A4.x -= W20 * xr.x; A4.y -= W20 * xr.y; A4.z -= W20 * xr.z; A4.w -= W20 * xr.w;
        A5.x -= W21 * xr.x; A5.y -= W21 * xr.y; A5.z -= W21 * xr.z; A5.w -= W21 * xr.w;
        A6.x -= W22 * xr.x; A6.y -= W22 * xr.y; A6.z -= W22 * xr.z; A6.w -= W22 * xr.w;
        A7.x -= W23 * xr.x; A7.y -= W23 * xr.y; A7.z -= W23 * xr.z; A7.w -= W23 * xr.w;
    }

    // write: half 0 -> channels 0..3 (radial), half 1 -> channels 4..7 (tangential)
    if (half == 0) {
        Ar4[0 * 16 + hl] = A0;
        Ar4[1 * 16 + hl] = A1;
        Ar4[2 * 16 + hl] = A2;
        Ar4[3 * 16 + hl] = A3;
    } else {
        Ar4[4 * 16 + hl] = A4;
        Ar4[5 * 16 + hl] = A5;
        Ar4[6 * 16 + hl] = A6;
        Ar4[7 * 16 + hl] = A7;
    }
}

// ------------------- K7: out = x + A @ M  (fused proj + head-mean + w_out) ----
#define PNB 64
__global__ void __launch_bounds__(256) k_post(const float* __restrict__ x,
                                              float* __restrict__ out,
                                              int n_nodes) {
    int tid = threadIdx.x;
    int ng  = tid >> 4;
    int goq = tid & 15;
    int n0 = blockIdx.x * PNB + ng * 4;

    const float4* Mp = (const float4*)g_M;
    float4 acc0 = {0,0,0,0}, acc1 = {0,0,0,0}, acc2 = {0,0,0,0}, acc3 = {0,0,0,0};

    const float* A0 = &g_A[(size_t)n0 * 512];

#pragma unroll 2
    for (int k = 0; k < 512; k += 4) {
        float4 m0 = __ldg(&Mp[(k + 0) * 16 + goq]);
        float4 m1 = __ldg(&Mp[(k + 1) * 16 + goq]);
        float4 m2 = __ldg(&Mp[(k + 2) * 16 + goq]);
        float4 m3 = __ldg(&Mp[(k + 3) * 16 + goq]);
        float4 a0 = *(const float4*)&A0[0 * 512 + k];
        float4 a1 = *(const float4*)&A0[1 * 512 + k];
        float4 a2 = *(const float4*)&A0[2 * 512 + k];
        float4 a3 = *(const float4*)&A0[3 * 512 + k];
        acc0.x += a0.x * m0.x + a0.y * m1.x + a0.z * m2.x + a0.w * m3.x;
        acc0.y += a0.x * m0.y + a0.y * m1.y + a0.z * m2.y + a0.w * m3.y;
        acc0.z += a0.x * m0.z + a0.y * m1.z + a0.z * m2.z + a0.w * m3.z;
        acc0.w += a0.x * m0.w + a0.y * m1.w + a0.z * m2.w + a0.w * m3.w;
        acc1.x += a1.x * m0.x + a1.y * m1.x + a1.z * m2.x + a1.w * m3.x;
        acc1.y += a1.x * m0.y + a1.y * m1.y + a1.z * m2.y + a1.w * m3.y;
        acc1.z += a1.x * m0.z + a1.y * m1.z + a1.z * m2.z + a1.w * m3.z;
        acc1.w += a1.x * m0.w + a1.y * m1.w + a1.z * m2.w + a1.w * m3.w;
        acc2.x += a2.x * m0.x + a2.y * m1.x + a2.z * m2.x + a2.w * m3.x;
        acc2.y += a2.x * m0.y + a2.y * m1.y + a2.z * m2.y + a2.w * m3.y;
        acc2.z += a2.x * m0.z + a2.y * m1.z + a2.z * m2.z + a2.w * m3.z;
        acc2.w += a2.x * m0.w + a2.y * m1.w + a2.z * m2.w + a2.w * m3.w;
        acc3.x += a3.x * m0.x + a3.y * m1.x + a3.z * m2.x + a3.w * m3.x;
        acc3.y += a3.x * m0.y + a3.y * m1.y + a3.z * m2.y + a3.w * m3.y;
        acc3.z += a3.x * m0.z + a3.y * m1.z + a3.z * m2.z + a3.w * m3.z;
        acc3.w += a3.x * m0.w + a3.y * m1.w + a3.z * m2.w + a3.w * m3.w;
    }

    float4 accs[4] = {acc0, acc1, acc2, acc3};
#pragma unroll
    for (int j = 0; j < 4; j++) {
        int n = n0 + j;
        if (n >= n_nodes) break;
        float4 xv = *(const float4*)&x[n * F + goq * 4];
        float4 o;
        o.x = xv.x + accs[j].x;
        o.y = xv.y + accs[j].y;
        o.z = xv.z + accs[j].z;
        o.w = xv.w + accs[j].w;
        *(float4*)&out[n * F + goq * 4] = o;
    }
}

// ------------------- launch -------------------
extern "C" void kernel_launch(void* const* d_in, const int* in_sizes, int n_in,
                              void* d_out, int out_size) {
    const float* x     = (const float*)d_in[0];
    const int*   ei    = (const int*)d_in[1];     // edge_index staged as int32, [2, E]
    // d_in[2] = edge_vec (unused by reference)
    const float* elen  = (const float*)d_in[3];
    const float* wprj  = (const float*)d_in[4];
    const float* wrad  = (const float*)d_in[5];
    const float* wtan  = (const float*)d_in[6];
    const float* rsc   = (const float*)d_in[7];
    const float* tsc   = (const float*)d_in[8];
    const float* rdls  = (const float*)d_in[9];
    const float* rtb   = (const float*)d_in[10];
    const float* rtw   = (const float*)d_in[11];
    const float* mixb  = (const float*)d_in[12];
    const float* mixs  = (const float*)d_in[13];
    const float* wout  = (const float*)d_in[14];
    float*       out   = (float*)d_out;

    int n_nodes = in_sizes[0] / F;
    int n_edges = in_sizes[3];

    k_setup<<<9 + (n_nodes + 255) / 256, 256>>>(wrad, wtan, wout,
                                                wprj, rsc, tsc, n_nodes);
    k_scal<<<(n_nodes + SNB - 1) / SNB, 256>>>(x, n_nodes);

    int ethreads = (n_edges + 3) / 4;
    k_hist<<<(ethreads + 255) / 256, 256>>>(ei, n_edges, n_nodes);

    int sblocks = (n_nodes + SCB - 1) / SCB;
    k_scan1<<<sblocks, 256>>>(n_nodes);
    k_scan2<<<sblocks, 256>>>(n_nodes, sblocks);

    k_sort<<<(ethreads + 255) / 256, 256>>>(ei, elen, n_edges, n_nodes);

    k_main<<<(n_nodes * 32 + 255) / 256, 256>>>(x, rdls, rtb, rtw, mixb, mixs, n_nodes);
    k_post<<<(n_nodes + PNB - 1) / PNB, 256>>>(x, out, n_nodes);
}